// round 10
// baseline (speedup 1.0000x reference)
#include <cuda_runtime.h>

#define NUM_GRAPHS 2048
#define ND 256
#define ED 128
#define HD 128
#define MAXN 100000

// Scratch (device globals: allocation-free per harness rules)
__device__ __align__(16) int   g_offsets[NUM_GRAPHS + 1];
__device__ __align__(16) float g_P[NUM_GRAPHS * HD];         // pooled @ W1d   [2048,128]
__device__ __align__(16) float g_AB[(size_t)MAXN * 256];     // [h@W1a | h@W1b] [N,256]

// ---------------------------------------------------------------------------
// Kernel 1: graph start offsets via binary search (batch is sorted int32)
// ---------------------------------------------------------------------------
__global__ void offsets_kernel(const int* __restrict__ batch, int N) {
    int g = blockIdx.x * blockDim.x + threadIdx.x;
    if (g > NUM_GRAPHS) return;
    int lo = 0, hi = N;
    while (lo < hi) {
        int mid = (lo + hi) >> 1;
        if (batch[mid] < g) lo = mid + 1; else hi = mid;
    }
    g_offsets[g] = lo;
}

// ---------------------------------------------------------------------------
// Kernel 2: per-graph mean pooling + P = pooled @ W1d (W1 rows 640..895)
// ---------------------------------------------------------------------------
__global__ void pool_kernel(const float* __restrict__ h, const float* __restrict__ W1) {
    __shared__ float pool_s[ND];
    int g = blockIdx.x;
    int tid = threadIdx.x;
    int o0 = g_offsets[g], o1 = g_offsets[g + 1];
    float s0 = 0.f, s1 = 0.f;
    for (int r = o0; r < o1; ++r) {
        const float* row = h + (size_t)r * ND;
        s0 += row[tid];
        s1 += row[tid + 128];
    }
    int cnt = o1 - o0;
    float inv = 1.f / (float)(cnt > 1 ? cnt : 1);
    pool_s[tid]       = s0 * inv;
    pool_s[tid + 128] = s1 * inv;
    __syncthreads();
    float acc = 0.f;
    const float* Wg = W1 + (size_t)640 * HD;
#pragma unroll 8
    for (int k = 0; k < ND; ++k) acc += pool_s[k] * Wg[k * HD + tid];
    g_P[g * HD + tid] = acc;
}

// ---------------------------------------------------------------------------
// Kernel 3: pipelined node GEMM. C[m, cbase..cbase+127] = A[m,:K] @ W[:K,:128]
// BM=128, BN=128, BK=8; 256 threads; 8x8/thread; double-buffered smem,
// register prefetch of next k-tile during compute. One sync per k-tile.
// ---------------------------------------------------------------------------
template<int K>
__global__ void node_gemm_kernel(const float* __restrict__ A, int lda,
                                 const float* __restrict__ W,
                                 float* __restrict__ C, int ldc, int cbase,
                                 int M) {
    __shared__ float aT_s[2][8][132];
    __shared__ float w_s[2][8][132];
    int tid = threadIdx.x;            // 256
    int m0  = blockIdx.x * 128;
    int r0 = (tid >> 4) * 8;
    int c0 = (tid & 15) * 8;

    float acc[8][8];
#pragma unroll
    for (int i = 0; i < 8; ++i)
#pragma unroll
        for (int j = 0; j < 8; ++j) acc[i][j] = 0.f;

    int lrow = tid >> 1;              // 0..127 (A row within tile)
    int lcol = (tid & 1) * 4;         // 0 or 4 (k within tile)
    int wrow = tid >> 5;              // 0..7   (k within tile)
    int wcol = (tid & 31) * 4;        // 0..124 (W col)

    int mA = m0 + lrow;
    const float* Aptr = A + (size_t)mA * lda + lcol;
    const float* Wptr = W + (size_t)wrow * 128 + wcol;

    // prefetch k-tile 0
    float4 av = make_float4(0.f, 0.f, 0.f, 0.f);
    if (mA < M) av = *(const float4*)(Aptr);
    float4 wv = *(const float4*)(Wptr);

    int buf = 0;
    for (int kt = 0; kt < K; kt += 8) {
        aT_s[buf][lcol + 0][lrow] = av.x;
        aT_s[buf][lcol + 1][lrow] = av.y;
        aT_s[buf][lcol + 2][lrow] = av.z;
        aT_s[buf][lcol + 3][lrow] = av.w;
        *(float4*)&w_s[buf][wrow][wcol] = wv;
        __syncthreads();

        if (kt + 8 < K) {
            if (mA < M) av = *(const float4*)(Aptr + kt + 8);
            wv = *(const float4*)(Wptr + (size_t)(kt + 8) * 128);
        }

#pragma unroll
        for (int k = 0; k < 8; ++k) {
            float a[8], b[8];
            *(float4*)&a[0] = *(const float4*)&aT_s[buf][k][r0];
            *(float4*)&a[4] = *(const float4*)&aT_s[buf][k][r0 + 4];
            *(float4*)&b[0] = *(const float4*)&w_s[buf][k][c0];
            *(float4*)&b[4] = *(const float4*)&w_s[buf][k][c0 + 4];
#pragma unroll
            for (int i = 0; i < 8; ++i)
#pragma unroll
                for (int j = 0; j < 8; ++j) acc[i][j] += a[i] * b[j];
        }
        buf ^= 1;
    }

#pragma unroll
    for (int i = 0; i < 8; ++i) {
        int m = m0 + r0 + i;
        if (m < M) {
            float* dst = C + (size_t)m * ldc + cbase + c0;
            *(float4*)dst       = make_float4(acc[i][0], acc[i][1], acc[i][2], acc[i][3]);
            *(float4*)(dst + 4) = make_float4(acc[i][4], acc[i][5], acc[i][6], acc[i][7]);
        }
    }
}

// ---------------------------------------------------------------------------
// Kernel 4: fused edge GEMM + epilogue.
//   acc[128e x 128h] = ea_tile @ W1c      (pipelined, as above, K=128)
//   hid = relu(acc + AB[s][0:128] + AB[t][128:256] + P[batch[s]] + b1)
//   out[e] = hid . W2 + b2     (16-lane shfl reduce, lanes share a row)
// ---------------------------------------------------------------------------
__global__ void edge_gemm_fused_kernel(const float* __restrict__ ea,
                                       const int* __restrict__ ei,
                                       const int* __restrict__ batch,
                                       const float* __restrict__ W1,
                                       const float* __restrict__ b1,
                                       const float* __restrict__ W2,
                                       const float* __restrict__ b2,
                                       float* __restrict__ out, int E) {
    __shared__ float aT_s[2][8][132];
    __shared__ float w_s[2][8][132];
    __shared__ int   sidx[128], tidx[128], bidx[128];
    __shared__ float b1_s[128], W2_s[128];

    const float* Wc = W1 + (size_t)512 * 128;
    int tid = threadIdx.x;            // 256
    int e0  = blockIdx.x * 128;
    int ty  = tid >> 4;
    int tx  = tid & 15;
    int r0  = ty * 8;
    int c0  = tx * 8;

    if (tid < 128) {
        b1_s[tid] = b1[tid];
        W2_s[tid] = W2[tid];
        int e = e0 + tid;
        int s = 0, t = 0, b = 0;
        if (e < E) {
            s = __ldg(&ei[e]);
            t = __ldg(&ei[E + e]);
            b = __ldg(&batch[s]);
        }
        sidx[tid] = s; tidx[tid] = t; bidx[tid] = b;
    }

    float acc[8][8];
#pragma unroll
    for (int i = 0; i < 8; ++i)
#pragma unroll
        for (int j = 0; j < 8; ++j) acc[i][j] = 0.f;

    int lrow = tid >> 1;
    int lcol = (tid & 1) * 4;
    int wrow = tid >> 5;
    int wcol = (tid & 31) * 4;

    int eA = e0 + lrow;
    const float* Aptr = ea + (size_t)eA * ED + lcol;
    const float* Wptr = Wc + (size_t)wrow * 128 + wcol;

    float4 av = make_float4(0.f, 0.f, 0.f, 0.f);
    if (eA < E) av = *(const float4*)(Aptr);
    float4 wv = *(const float4*)(Wptr);

    int buf = 0;
    for (int kt = 0; kt < 128; kt += 8) {
        aT_s[buf][lcol + 0][lrow] = av.x;
        aT_s[buf][lcol + 1][lrow] = av.y;
        aT_s[buf][lcol + 2][lrow] = av.z;
        aT_s[buf][lcol + 3][lrow] = av.w;
        *(float4*)&w_s[buf][wrow][wcol] = wv;
        __syncthreads();

        if (kt + 8 < 128) {
            if (eA < E) av = *(const float4*)(Aptr + kt + 8);
            wv = *(const float4*)(Wptr + (size_t)(kt + 8) * 128);
        }

#pragma unroll
        for (int k = 0; k < 8; ++k) {
            float a[8], b[8];
            *(float4*)&a[0] = *(const float4*)&aT_s[buf][k][r0];
            *(float4*)&a[4] = *(const float4*)&aT_s[buf][k][r0 + 4];
            *(float4*)&b[0] = *(const float4*)&w_s[buf][k][c0];
            *(float4*)&b[4] = *(const float4*)&w_s[buf][k][c0 + 4];
#pragma unroll
            for (int i = 0; i < 8; ++i)
#pragma unroll
                for (int j = 0; j < 8; ++j) acc[i][j] += a[i] * b[j];
        }
        buf ^= 1;
    }

    // Epilogue: gather node/pool terms, relu, dot with W2, 16-lane reduce
    float b2v = __ldg(b2);
    float w2r[8];
    *(float4*)&w2r[0] = *(const float4*)&W2_s[c0];
    *(float4*)&w2r[4] = *(const float4*)&W2_s[c0 + 4];
    float b1r[8];
    *(float4*)&b1r[0] = *(const float4*)&b1_s[c0];
    *(float4*)&b1r[4] = *(const float4*)&b1_s[c0 + 4];

#pragma unroll
    for (int i = 0; i < 8; ++i) {
        int r = r0 + i;
        int e = e0 + r;
        int s = sidx[r], t = tidx[r], b = bidx[r];
        const float4* Ap = (const float4*)(g_AB + (size_t)s * 256 + c0);
        const float4* Bp = (const float4*)(g_AB + (size_t)t * 256 + 128 + c0);
        const float4* Pp = (const float4*)(g_P + b * 128 + c0);
        float partial = 0.f;
#pragma unroll
        for (int jj = 0; jj < 2; ++jj) {
            float4 avv = __ldg(Ap + jj);
            float4 bvv = __ldg(Bp + jj);
            float4 pvv = __ldg(Pp + jj);
            const float* af = (const float*)&avv;
            const float* bf = (const float*)&bvv;
            const float* pf = (const float*)&pvv;
#pragma unroll
            for (int l = 0; l < 4; ++l) {
                int j = jj * 4 + l;
                float v = acc[i][j] + af[l] + bf[l] + pf[l] + b1r[j];
                partial += fmaxf(v, 0.f) * w2r[j];
            }
        }
#pragma unroll
        for (int off = 1; off < 16; off <<= 1)
            partial += __shfl_xor_sync(0xffffffffu, partial, off);
        if (tx == 0 && e < E) out[e] = partial + b2v;
    }
}

// ---------------------------------------------------------------------------
extern "C" void kernel_launch(void* const* d_in, const int* in_sizes, int n_in,
                              void* d_out, int out_size) {
    const float* h     = (const float*)d_in[0];
    const int*   ei    = (const int*)d_in[1];     // int32 (JAX x64 disabled)
    const float* ea    = (const float*)d_in[2];
    const int*   batch = (const int*)d_in[3];     // int32
    const float* W1    = (const float*)d_in[4];
    const float* b1    = (const float*)d_in[5];
    const float* W2    = (const float*)d_in[6];
    const float* b2    = (const float*)d_in[7];
    float* out = (float*)d_out;

    int N = in_sizes[0] / ND;
    int E = in_sizes[2] / ED;

    offsets_kernel<<<(NUM_GRAPHS + 256) / 256, 256>>>(batch, N);
    pool_kernel<<<NUM_GRAPHS, 128>>>(h, W1);

    float* AB = nullptr; cudaGetSymbolAddress((void**)&AB, g_AB);

    int nblk = (N + 127) / 128;
    int eblk = (E + 127) / 128;
    // AB[:,0:128]   = h @ W1[0:256]
    node_gemm_kernel<256><<<nblk, 256>>>(h, ND, W1, AB, 256, 0, N);
    // AB[:,128:256] = h @ W1[256:512]
    node_gemm_kernel<256><<<nblk, 256>>>(h, ND, W1 + (size_t)256 * 128, AB, 256, 128, N);
    // fused: ea @ W1[512:640] + gather + relu + W2 dot
    edge_gemm_fused_kernel<<<eblk, 256>>>(ea, ei, batch, W1, b1, W2, b2, out, E);
}

// round 11
// speedup vs baseline: 2.1335x; 2.1335x over previous
#include <cuda_runtime.h>
#include <cuda_bf16.h>

#define NUM_GRAPHS 2048
#define ND 256
#define ED 128
#define HD 128
#define MAXN 100000

// Scratch (device globals: allocation-free per harness rules)
__device__ __align__(16) int   g_offsets[NUM_GRAPHS + 1];
__device__ __align__(16) float g_P[NUM_GRAPHS * HD];          // pooled @ W1d [2048,128]
__device__ __align__(16) float g_AB[(size_t)MAXN * 256];      // [h@W1a | h@W1b]
__device__ __align__(16) __nv_bfloat16 g_BnHi[256 * 256];     // [W1a|W1b] split, k-major
__device__ __align__(16) __nv_bfloat16 g_BnLo[256 * 256];
__device__ __align__(16) __nv_bfloat16 g_BeHi[128 * 128];     // W1c split, k-major
__device__ __align__(16) __nv_bfloat16 g_BeLo[128 * 128];

// ---------------------------------------------------------------------------
// mma/ldmatrix helpers
// ---------------------------------------------------------------------------
__device__ __forceinline__ unsigned smem_u32(const void* p) {
    return (unsigned)__cvta_generic_to_shared(p);
}
__device__ __forceinline__ void ldsm4(unsigned addr, unsigned& r0, unsigned& r1,
                                      unsigned& r2, unsigned& r3) {
    asm volatile("ldmatrix.sync.aligned.m8n8.x4.shared.b16 {%0,%1,%2,%3}, [%4];"
                 : "=r"(r0), "=r"(r1), "=r"(r2), "=r"(r3) : "r"(addr));
}
__device__ __forceinline__ void ldsm2t(unsigned addr, unsigned& r0, unsigned& r1) {
    asm volatile("ldmatrix.sync.aligned.m8n8.x2.trans.shared.b16 {%0,%1}, [%2];"
                 : "=r"(r0), "=r"(r1) : "r"(addr));
}
__device__ __forceinline__ void mma16816(float* c, const unsigned* a, const unsigned* b) {
    asm volatile("mma.sync.aligned.m16n8k16.row.col.f32.bf16.bf16.f32 "
                 "{%0,%1,%2,%3}, {%4,%5,%6,%7}, {%8,%9}, {%0,%1,%2,%3};"
                 : "+f"(c[0]), "+f"(c[1]), "+f"(c[2]), "+f"(c[3])
                 : "r"(a[0]), "r"(a[1]), "r"(a[2]), "r"(a[3]), "r"(b[0]), "r"(b[1]));
}
__device__ __forceinline__ void split2(float x0, float x1, unsigned& hi, unsigned& lo) {
    __nv_bfloat16 h0 = __float2bfloat16(x0), h1 = __float2bfloat16(x1);
    __nv_bfloat16 l0 = __float2bfloat16(x0 - __bfloat162float(h0));
    __nv_bfloat16 l1 = __float2bfloat16(x1 - __bfloat162float(h1));
    __nv_bfloat162 H = __nv_bfloat162(h0, h1), L = __nv_bfloat162(l0, l1);
    hi = *(unsigned*)&H;
    lo = *(unsigned*)&L;
}

// ---------------------------------------------------------------------------
// Kernel 0: split weights into bf16 hi/lo (k-major, same layout as W1 rows)
// ---------------------------------------------------------------------------
__global__ void prep_kernel(const float* __restrict__ W1) {
    int idx = blockIdx.x * blockDim.x + threadIdx.x;
    if (idx < 256 * 256) {
        int k = idx >> 8, n = idx & 255;
        float w = (n < 128) ? W1[(size_t)k * 128 + n]
                            : W1[(size_t)(256 + k) * 128 + (n - 128)];
        __nv_bfloat16 hi = __float2bfloat16(w);
        g_BnHi[idx] = hi;
        g_BnLo[idx] = __float2bfloat16(w - __bfloat162float(hi));
    }
    if (idx < 128 * 128) {
        int k = idx >> 7, n = idx & 127;
        float w = W1[(size_t)(512 + k) * 128 + n];
        __nv_bfloat16 hi = __float2bfloat16(w);
        g_BeHi[idx] = hi;
        g_BeLo[idx] = __float2bfloat16(w - __bfloat162float(hi));
    }
}

// ---------------------------------------------------------------------------
// Kernel 1: graph start offsets via binary search (batch is sorted int32)
// ---------------------------------------------------------------------------
__global__ void offsets_kernel(const int* __restrict__ batch, int N) {
    int g = blockIdx.x * blockDim.x + threadIdx.x;
    if (g > NUM_GRAPHS) return;
    int lo = 0, hi = N;
    while (lo < hi) {
        int mid = (lo + hi) >> 1;
        if (batch[mid] < g) lo = mid + 1; else hi = mid;
    }
    g_offsets[g] = lo;
}

// ---------------------------------------------------------------------------
// Kernel 2: per-graph mean pooling + P = pooled @ W1d (W1 rows 640..895)
// ---------------------------------------------------------------------------
__global__ void pool_kernel(const float* __restrict__ h, const float* __restrict__ W1) {
    __shared__ float pool_s[ND];
    int g = blockIdx.x;
    int tid = threadIdx.x;
    int o0 = g_offsets[g], o1 = g_offsets[g + 1];
    float s0 = 0.f, s1 = 0.f;
    for (int r = o0; r < o1; ++r) {
        const float* row = h + (size_t)r * ND;
        s0 += row[tid];
        s1 += row[tid + 128];
    }
    int cnt = o1 - o0;
    float inv = 1.f / (float)(cnt > 1 ? cnt : 1);
    pool_s[tid]       = s0 * inv;
    pool_s[tid + 128] = s1 * inv;
    __syncthreads();
    float acc = 0.f;
    const float* Wg = W1 + (size_t)640 * HD;
#pragma unroll 8
    for (int k = 0; k < ND; ++k) acc += pool_s[k] * Wg[k * HD + tid];
    g_P[g * HD + tid] = acc;
}

// ---------------------------------------------------------------------------
// Kernel 3: node GEMM via bf16-split mma: AB[m,0:256] = h[m,0:256] @ Bcat
// block tile 128m x 256n, K=256 in steps of 16. 512 threads = 16 warps (4m x 4n),
// warp tile 32m x 64n. hi*hi + lo*hi + hi*lo accumulation.
// ---------------------------------------------------------------------------
__global__ __launch_bounds__(512) void node_gemm_bf16(const float* __restrict__ h,
                                                      float* __restrict__ AB, int M) {
    __shared__ __nv_bfloat16 Ahi[128 * 24], Alo[128 * 24];     // m-major, ld=24
    __shared__ __nv_bfloat16 Bhi[16 * 264], Blo[16 * 264];     // k-major, ld=264
    int tid = threadIdx.x;
    int wid = tid >> 5, lane = tid & 31;
    int wm = (wid & 3) * 32, wn = (wid >> 2) * 64;
    int m0 = blockIdx.x * 128;

    float c[2][8][4];
#pragma unroll
    for (int mf = 0; mf < 2; ++mf)
#pragma unroll
        for (int nf = 0; nf < 8; ++nf)
#pragma unroll
            for (int q = 0; q < 4; ++q) c[mf][nf][q] = 0.f;

    int l15 = lane & 15, l16 = lane >> 4;
    unsigned aHiA[2], aLoA[2];
#pragma unroll
    for (int mf = 0; mf < 2; ++mf) {
        unsigned off = ((wm + mf * 16 + l15) * 24 + l16 * 8) * 2;
        aHiA[mf] = smem_u32(Ahi) + off;
        aLoA[mf] = smem_u32(Alo) + off;
    }
    unsigned bHiA = smem_u32(Bhi) + (l15 * 264 + wn) * 2;
    unsigned bLoA = smem_u32(Blo) + (l15 * 264 + wn) * 2;

    int am = tid >> 2, kq = tid & 3;           // A loader role
    int br = tid >> 5, bc = (tid & 31) * 8;    // B loader role

    for (int kt = 0; kt < 16; ++kt) {
        float4 v = make_float4(0.f, 0.f, 0.f, 0.f);
        if (m0 + am < M)
            v = *(const float4*)(h + (size_t)(m0 + am) * 256 + kt * 16 + kq * 4);
        unsigned h01, l01, h23, l23;
        split2(v.x, v.y, h01, l01);
        split2(v.z, v.w, h23, l23);
        *(uint2*)&Ahi[am * 24 + kq * 4] = make_uint2(h01, h23);
        *(uint2*)&Alo[am * 24 + kq * 4] = make_uint2(l01, l23);

        *(uint4*)&Bhi[br * 264 + bc] = *(const uint4*)&g_BnHi[(kt * 16 + br) * 256 + bc];
        *(uint4*)&Blo[br * 264 + bc] = *(const uint4*)&g_BnLo[(kt * 16 + br) * 256 + bc];
        __syncthreads();

        unsigned ah[2][4], al[2][4];
        ldsm4(aHiA[0], ah[0][0], ah[0][1], ah[0][2], ah[0][3]);
        ldsm4(aHiA[1], ah[1][0], ah[1][1], ah[1][2], ah[1][3]);
        ldsm4(aLoA[0], al[0][0], al[0][1], al[0][2], al[0][3]);
        ldsm4(aLoA[1], al[1][0], al[1][1], al[1][2], al[1][3]);
#pragma unroll
        for (int nf = 0; nf < 8; ++nf) {
            unsigned bh[2], bl[2];
            ldsm2t(bHiA + nf * 16, bh[0], bh[1]);
            ldsm2t(bLoA + nf * 16, bl[0], bl[1]);
#pragma unroll
            for (int mf = 0; mf < 2; ++mf) {
                mma16816(c[mf][nf], ah[mf], bh);
                mma16816(c[mf][nf], al[mf], bh);
                mma16816(c[mf][nf], ah[mf], bl);
            }
        }
        __syncthreads();
    }

    int r = lane >> 2, q = (lane & 3) * 2;
#pragma unroll
    for (int mf = 0; mf < 2; ++mf)
#pragma unroll
        for (int nf = 0; nf < 8; ++nf) {
            int m = m0 + wm + mf * 16 + r;
            int n = wn + nf * 8 + q;
            if (m < M)
                *(float2*)&AB[(size_t)m * 256 + n] = make_float2(c[mf][nf][0], c[mf][nf][1]);
            if (m + 8 < M)
                *(float2*)&AB[(size_t)(m + 8) * 256 + n] = make_float2(c[mf][nf][2], c[mf][nf][3]);
        }
}

// ---------------------------------------------------------------------------
// Kernel 4: fused edge GEMM (bf16-split mma) + epilogue.
// block tile 128e x 128n, K=128 in steps of 16. 256 threads = 8 warps (4m x 2n).
//   hid = relu(acc + AB[s][0:128] + AB[t][128:256] + P[batch[s]] + b1)
//   out[e] = hid . W2 + b2
// ---------------------------------------------------------------------------
__global__ __launch_bounds__(256) void edge_gemm_fused(const float* __restrict__ ea,
                                                       const int* __restrict__ ei,
                                                       const int* __restrict__ batch,
                                                       const float* __restrict__ b1,
                                                       const float* __restrict__ W2,
                                                       const float* __restrict__ b2,
                                                       float* __restrict__ out, int E) {
    __shared__ __nv_bfloat16 Ahi[128 * 24], Alo[128 * 24];     // ld=24
    __shared__ __nv_bfloat16 Bhi[16 * 136], Blo[16 * 136];     // ld=136
    __shared__ int sidx[128], tidx[128], bidx[128];
    __shared__ float outs[128], b1s[128], W2s[128];

    int tid = threadIdx.x;
    int wid = tid >> 5, lane = tid & 31;
    int wm = (wid & 3) * 32, wn = (wid >> 2) * 64;
    int e0 = blockIdx.x * 128;

    if (tid < 128) {
        b1s[tid] = b1[tid];
        W2s[tid] = W2[tid];
        outs[tid] = 0.f;
        int e = e0 + tid;
        int s = 0, t = 0, b = 0;
        if (e < E) {
            s = __ldg(&ei[e]);
            t = __ldg(&ei[E + e]);
            b = __ldg(&batch[s]);
        }
        sidx[tid] = s; tidx[tid] = t; bidx[tid] = b;
    }

    float c[2][8][4];
#pragma unroll
    for (int mf = 0; mf < 2; ++mf)
#pragma unroll
        for (int nf = 0; nf < 8; ++nf)
#pragma unroll
            for (int q = 0; q < 4; ++q) c[mf][nf][q] = 0.f;

    int l15 = lane & 15, l16 = lane >> 4;
    unsigned aHiA[2], aLoA[2];
#pragma unroll
    for (int mf = 0; mf < 2; ++mf) {
        unsigned off = ((wm + mf * 16 + l15) * 24 + l16 * 8) * 2;
        aHiA[mf] = smem_u32(Ahi) + off;
        aLoA[mf] = smem_u32(Alo) + off;
    }
    unsigned bHiA = smem_u32(Bhi) + (l15 * 136 + wn) * 2;
    unsigned bLoA = smem_u32(Blo) + (l15 * 136 + wn) * 2;

    int am = tid >> 1, half = tid & 1;         // A loader: 8 floats each
    int br = tid >> 4, bc = (tid & 15) * 8;    // B loader

    for (int kt = 0; kt < 8; ++kt) {
        float4 v0 = make_float4(0.f, 0.f, 0.f, 0.f), v1 = v0;
        if (e0 + am < E) {
            const float* src = ea + (size_t)(e0 + am) * 128 + kt * 16 + half * 8;
            v0 = *(const float4*)(src);
            v1 = *(const float4*)(src + 4);
        }
        unsigned h01, l01, h23, l23, h45, l45, h67, l67;
        split2(v0.x, v0.y, h01, l01);
        split2(v0.z, v0.w, h23, l23);
        split2(v1.x, v1.y, h45, l45);
        split2(v1.z, v1.w, h67, l67);
        *(uint4*)&Ahi[am * 24 + half * 8] = make_uint4(h01, h23, h45, h67);
        *(uint4*)&Alo[am * 24 + half * 8] = make_uint4(l01, l23, l45, l67);

        *(uint4*)&Bhi[br * 136 + bc] = *(const uint4*)&g_BeHi[(kt * 16 + br) * 128 + bc];
        *(uint4*)&Blo[br * 136 + bc] = *(const uint4*)&g_BeLo[(kt * 16 + br) * 128 + bc];
        __syncthreads();

        unsigned ah[2][4], al[2][4];
        ldsm4(aHiA[0], ah[0][0], ah[0][1], ah[0][2], ah[0][3]);
        ldsm4(aHiA[1], ah[1][0], ah[1][1], ah[1][2], ah[1][3]);
        ldsm4(aLoA[0], al[0][0], al[0][1], al[0][2], al[0][3]);
        ldsm4(aLoA[1], al[1][0], al[1][1], al[1][2], al[1][3]);
#pragma unroll
        for (int nf = 0; nf < 8; ++nf) {
            unsigned bh[2], bl[2];
            ldsm2t(bHiA + nf * 16, bh[0], bh[1]);
            ldsm2t(bLoA + nf * 16, bl[0], bl[1]);
#pragma unroll
            for (int mf = 0; mf < 2; ++mf) {
                mma16816(c[mf][nf], ah[mf], bh);
                mma16816(c[mf][nf], al[mf], bh);
                mma16816(c[mf][nf], ah[mf], bl);
            }
        }
        __syncthreads();
    }

    // Epilogue: per-row gather + relu + W2 dot, reduce over n
    int r = lane >> 2, q = (lane & 3) * 2;
    float b2v = __ldg(b2);
#pragma unroll
    for (int mf = 0; mf < 2; ++mf) {
#pragma unroll
        for (int half = 0; half < 2; ++half) {
            int row = wm + mf * 16 + half * 8 + r;
            int s = sidx[row], t = tidx[row], b = bidx[row];
            const float* As = g_AB + (size_t)s * 256;
            const float* Bs = g_AB + (size_t)t * 256 + 128;
            const float* Ps = g_P + b * 128;
            float partial = 0.f;
#pragma unroll
            for (int nf = 0; nf < 8; ++nf) {
                int n = wn + nf * 8 + q;
                float2 a2 = *(const float2*)(As + n);
                float2 bb = *(const float2*)(Bs + n);
                float2 p2 = *(const float2*)(Ps + n);
                float c0 = c[mf][nf][half * 2 + 0];
                float c1 = c[mf][nf][half * 2 + 1];
                float v0 = fmaxf(c0 + a2.x + bb.x + p2.x + b1s[n], 0.f) * W2s[n];
                float v1 = fmaxf(c1 + a2.y + bb.y + p2.y + b1s[n + 1], 0.f) * W2s[n + 1];
                partial += v0 + v1;
            }
            partial += __shfl_xor_sync(0xffffffffu, partial, 1);
            partial += __shfl_xor_sync(0xffffffffu, partial, 2);
            if ((lane & 3) == 0) atomicAdd(&outs[row], partial);
        }
    }
    __syncthreads();
    if (tid < 128) {
        int e = e0 + tid;
        if (e < E) out[e] = outs[tid] + b2v;
    }
}

// ---------------------------------------------------------------------------
extern "C" void kernel_launch(void* const* d_in, const int* in_sizes, int n_in,
                              void* d_out, int out_size) {
    const float* h     = (const float*)d_in[0];
    const int*   ei    = (const int*)d_in[1];     // int32 (JAX x64 disabled)
    const float* ea    = (const float*)d_in[2];
    const int*   batch = (const int*)d_in[3];     // int32
    const float* W1    = (const float*)d_in[4];
    const float* b1    = (const float*)d_in[5];
    const float* W2    = (const float*)d_in[6];
    const float* b2    = (const float*)d_in[7];
    float* out = (float*)d_out;

    int N = in_sizes[0] / ND;
    int E = in_sizes[2] / ED;

    prep_kernel<<<(256 * 256 + 255) / 256, 256>>>(W1);
    offsets_kernel<<<(NUM_GRAPHS + 256) / 256, 256>>>(batch, N);
    pool_kernel<<<NUM_GRAPHS, 128>>>(h, W1);

    float* AB = nullptr; cudaGetSymbolAddress((void**)&AB, g_AB);

    int nblk = (N + 127) / 128;
    int eblk = (E + 127) / 128;
    node_gemm_bf16<<<nblk, 512>>>(h, AB, N);
    edge_gemm_fused<<<eblk, 256>>>(ea, ei, batch, b1, W2, b2, out, E);
}

// round 12
// speedup vs baseline: 2.5297x; 1.1857x over previous
#include <cuda_runtime.h>
#include <cuda_bf16.h>

#define NUM_GRAPHS 2048
#define ND 256
#define ED 128
#define HD 128
#define MAXN 100000

// Scratch (device globals: allocation-free per harness rules)
__device__ __align__(16) int   g_offsets[NUM_GRAPHS + 1];
__device__ __align__(16) float g_P[NUM_GRAPHS * HD];          // pooled @ W1d [2048,128]
__device__ __align__(16) float g_AB[(size_t)MAXN * 256];      // [h@W1a | h@W1b]
__device__ __align__(16) __nv_bfloat16 g_BnHi[256 * 256];     // [W1a|W1b] split, k-major
__device__ __align__(16) __nv_bfloat16 g_BnLo[256 * 256];
__device__ __align__(16) __nv_bfloat16 g_BeHi[128 * 128];     // W1c split, k-major
__device__ __align__(16) __nv_bfloat16 g_BeLo[128 * 128];

// ---------------------------------------------------------------------------
// mma/ldmatrix helpers
// ---------------------------------------------------------------------------
__device__ __forceinline__ unsigned smem_u32(const void* p) {
    return (unsigned)__cvta_generic_to_shared(p);
}
__device__ __forceinline__ void ldsm4(unsigned addr, unsigned& r0, unsigned& r1,
                                      unsigned& r2, unsigned& r3) {
    asm volatile("ldmatrix.sync.aligned.m8n8.x4.shared.b16 {%0,%1,%2,%3}, [%4];"
                 : "=r"(r0), "=r"(r1), "=r"(r2), "=r"(r3) : "r"(addr));
}
__device__ __forceinline__ void ldsm2t(unsigned addr, unsigned& r0, unsigned& r1) {
    asm volatile("ldmatrix.sync.aligned.m8n8.x2.trans.shared.b16 {%0,%1}, [%2];"
                 : "=r"(r0), "=r"(r1) : "r"(addr));
}
__device__ __forceinline__ void mma16816(float* c, const unsigned* a, const unsigned* b) {
    asm volatile("mma.sync.aligned.m16n8k16.row.col.f32.bf16.bf16.f32 "
                 "{%0,%1,%2,%3}, {%4,%5,%6,%7}, {%8,%9}, {%0,%1,%2,%3};"
                 : "+f"(c[0]), "+f"(c[1]), "+f"(c[2]), "+f"(c[3])
                 : "r"(a[0]), "r"(a[1]), "r"(a[2]), "r"(a[3]), "r"(b[0]), "r"(b[1]));
}
__device__ __forceinline__ void split2(float x0, float x1, unsigned& hi, unsigned& lo) {
    __nv_bfloat16 h0 = __float2bfloat16(x0), h1 = __float2bfloat16(x1);
    __nv_bfloat16 l0 = __float2bfloat16(x0 - __bfloat162float(h0));
    __nv_bfloat16 l1 = __float2bfloat16(x1 - __bfloat162float(h1));
    __nv_bfloat162 H = __nv_bfloat162(h0, h1), L = __nv_bfloat162(l0, l1);
    hi = *(unsigned*)&H;
    lo = *(unsigned*)&L;
}

// ---------------------------------------------------------------------------
// Kernel 0: split weights into bf16 hi/lo (k-major)
// ---------------------------------------------------------------------------
__global__ void prep_kernel(const float* __restrict__ W1) {
    int idx = blockIdx.x * blockDim.x + threadIdx.x;
    if (idx < 256 * 256) {
        int k = idx >> 8, n = idx & 255;
        float w = (n < 128) ? W1[(size_t)k * 128 + n]
                            : W1[(size_t)(256 + k) * 128 + (n - 128)];
        __nv_bfloat16 hi = __float2bfloat16(w);
        g_BnHi[idx] = hi;
        g_BnLo[idx] = __float2bfloat16(w - __bfloat162float(hi));
    }
    if (idx < 128 * 128) {
        int k = idx >> 7, n = idx & 127;
        float w = W1[(size_t)(512 + k) * 128 + n];
        __nv_bfloat16 hi = __float2bfloat16(w);
        g_BeHi[idx] = hi;
        g_BeLo[idx] = __float2bfloat16(w - __bfloat162float(hi));
    }
}

// ---------------------------------------------------------------------------
// Kernel 1: graph start offsets via binary search (batch is sorted int32)
// ---------------------------------------------------------------------------
__global__ void offsets_kernel(const int* __restrict__ batch, int N) {
    int g = blockIdx.x * blockDim.x + threadIdx.x;
    if (g > NUM_GRAPHS) return;
    int lo = 0, hi = N;
    while (lo < hi) {
        int mid = (lo + hi) >> 1;
        if (batch[mid] < g) lo = mid + 1; else hi = mid;
    }
    g_offsets[g] = lo;
}

// ---------------------------------------------------------------------------
// Kernel 2: per-graph mean pooling + P = pooled @ W1d (W1 rows 640..895)
// ---------------------------------------------------------------------------
__global__ void pool_kernel(const float* __restrict__ h, const float* __restrict__ W1) {
    __shared__ float pool_s[ND];
    int g = blockIdx.x;
    int tid = threadIdx.x;
    int o0 = g_offsets[g], o1 = g_offsets[g + 1];
    float s0 = 0.f, s1 = 0.f;
    int r = o0;
    for (; r + 1 < o1; r += 2) {
        const float* row0 = h + (size_t)r * ND;
        const float* row1 = row0 + ND;
        s0 += row0[tid] + row1[tid];
        s1 += row0[tid + 128] + row1[tid + 128];
    }
    if (r < o1) {
        const float* row = h + (size_t)r * ND;
        s0 += row[tid];
        s1 += row[tid + 128];
    }
    int cnt = o1 - o0;
    float inv = 1.f / (float)(cnt > 1 ? cnt : 1);
    pool_s[tid]       = s0 * inv;
    pool_s[tid + 128] = s1 * inv;
    __syncthreads();
    float acc = 0.f;
    const float* Wg = W1 + (size_t)640 * HD;
#pragma unroll 8
    for (int k = 0; k < ND; ++k) acc += pool_s[k] * Wg[k * HD + tid];
    g_P[g * HD + tid] = acc;
}

// ---------------------------------------------------------------------------
// Kernel 3: node GEMM (double-buffered, reg-prefetch, one sync/k-tile).
// block tile 128m x 128n (grid.y selects AB half), 256 thr = 8 warps (4m x 2n).
// ---------------------------------------------------------------------------
__global__ __launch_bounds__(256, 2) void node_gemm_bf16(const float* __restrict__ h,
                                                         float* __restrict__ AB, int M) {
    __shared__ __nv_bfloat16 Ahi[2][128 * 24], Alo[2][128 * 24];
    __shared__ __nv_bfloat16 Bhi[2][16 * 136], Blo[2][16 * 136];

    int tid = threadIdx.x;
    int wid = tid >> 5, lane = tid & 31;
    int wm = (wid & 3) * 32, wn = (wid >> 2) * 64;
    int m0 = blockIdx.x * 128;
    int nb = blockIdx.y * 128;                 // AB column base / Bn column base
    const __nv_bfloat16* BHi = g_BnHi + nb;
    const __nv_bfloat16* BLo = g_BnLo + nb;

    float c[2][8][4];
#pragma unroll
    for (int mf = 0; mf < 2; ++mf)
#pragma unroll
        for (int nf = 0; nf < 8; ++nf)
#pragma unroll
            for (int q = 0; q < 4; ++q) c[mf][nf][q] = 0.f;

    int l15 = lane & 15, l16 = lane >> 4;
    unsigned aOff = ((wm + l15) * 24 + l16 * 8) * 2;
    unsigned bOff = (l15 * 136 + wn) * 2;

    int am = tid >> 1, half = tid & 1;         // A loader: 8 floats
    int br = tid >> 4, bc = (tid & 15) * 8;    // B loader: 8 bf16 x2

    const float* Aptr = h + (size_t)(m0 + am) * 256 + half * 8;
    bool aValid = (m0 + am) < M;

    // prologue: tile 0
    float4 v0 = make_float4(0.f, 0.f, 0.f, 0.f), v1 = v0;
    if (aValid) { v0 = *(const float4*)(Aptr); v1 = *(const float4*)(Aptr + 4); }
    uint4 bh = *(const uint4*)&BHi[(size_t)br * 256 + bc];
    uint4 bl = *(const uint4*)&BLo[(size_t)br * 256 + bc];
    {
        unsigned h01, l01, h23, l23, h45, l45, h67, l67;
        split2(v0.x, v0.y, h01, l01); split2(v0.z, v0.w, h23, l23);
        split2(v1.x, v1.y, h45, l45); split2(v1.z, v1.w, h67, l67);
        *(uint4*)&Ahi[0][am * 24 + half * 8] = make_uint4(h01, h23, h45, h67);
        *(uint4*)&Alo[0][am * 24 + half * 8] = make_uint4(l01, l23, l45, l67);
        *(uint4*)&Bhi[0][br * 136 + bc] = bh;
        *(uint4*)&Blo[0][br * 136 + bc] = bl;
    }
    __syncthreads();

    for (int kt = 0; kt < 16; ++kt) {
        int buf = kt & 1;
        // prefetch next tile (global -> regs)
        if (kt + 1 < 16) {
            if (aValid) {
                const float* src = Aptr + (kt + 1) * 16;
                v0 = *(const float4*)(src);
                v1 = *(const float4*)(src + 4);
            }
            bh = *(const uint4*)&BHi[(size_t)((kt + 1) * 16 + br) * 256 + bc];
            bl = *(const uint4*)&BLo[(size_t)((kt + 1) * 16 + br) * 256 + bc];
        }

        unsigned ah[2][4], al[2][4];
        unsigned aBase = smem_u32(Ahi[buf]), aBaseL = smem_u32(Alo[buf]);
        ldsm4(aBase + aOff,            ah[0][0], ah[0][1], ah[0][2], ah[0][3]);
        ldsm4(aBase + aOff + 16 * 48,  ah[1][0], ah[1][1], ah[1][2], ah[1][3]);
        ldsm4(aBaseL + aOff,           al[0][0], al[0][1], al[0][2], al[0][3]);
        ldsm4(aBaseL + aOff + 16 * 48, al[1][0], al[1][1], al[1][2], al[1][3]);
        unsigned bBase = smem_u32(Bhi[buf]) + bOff, bBaseL = smem_u32(Blo[buf]) + bOff;
#pragma unroll
        for (int nf = 0; nf < 8; ++nf) {
            unsigned bhr[2], blr[2];
            ldsm2t(bBase + nf * 16, bhr[0], bhr[1]);
            ldsm2t(bBaseL + nf * 16, blr[0], blr[1]);
#pragma unroll
            for (int mf = 0; mf < 2; ++mf) {
                mma16816(c[mf][nf], ah[mf], bhr);
                mma16816(c[mf][nf], al[mf], bhr);
                mma16816(c[mf][nf], ah[mf], blr);
            }
        }

        // convert + store next tile into other buffer
        if (kt + 1 < 16) {
            unsigned h01, l01, h23, l23, h45, l45, h67, l67;
            split2(v0.x, v0.y, h01, l01); split2(v0.z, v0.w, h23, l23);
            split2(v1.x, v1.y, h45, l45); split2(v1.z, v1.w, h67, l67);
            *(uint4*)&Ahi[buf ^ 1][am * 24 + half * 8] = make_uint4(h01, h23, h45, h67);
            *(uint4*)&Alo[buf ^ 1][am * 24 + half * 8] = make_uint4(l01, l23, l45, l67);
            *(uint4*)&Bhi[buf ^ 1][br * 136 + bc] = bh;
            *(uint4*)&Blo[buf ^ 1][br * 136 + bc] = bl;
        }
        __syncthreads();
    }

    int r = lane >> 2, q = (lane & 3) * 2;
#pragma unroll
    for (int mf = 0; mf < 2; ++mf)
#pragma unroll
        for (int nf = 0; nf < 8; ++nf) {
            int m = m0 + wm + mf * 16 + r;
            int n = nb + wn + nf * 8 + q;
            if (m < M)
                *(float2*)&AB[(size_t)m * 256 + n] = make_float2(c[mf][nf][0], c[mf][nf][1]);
            if (m + 8 < M)
                *(float2*)&AB[(size_t)(m + 8) * 256 + n] = make_float2(c[mf][nf][2], c[mf][nf][3]);
        }
}

// ---------------------------------------------------------------------------
// Kernel 4: fused edge GEMM (same pipeline) + epilogue.
// ---------------------------------------------------------------------------
__global__ __launch_bounds__(256, 2) void edge_gemm_fused(const float* __restrict__ ea,
                                                          const int* __restrict__ ei,
                                                          const int* __restrict__ batch,
                                                          const float* __restrict__ b1,
                                                          const float* __restrict__ W2,
                                                          const float* __restrict__ b2,
                                                          float* __restrict__ out, int E) {
    __shared__ __nv_bfloat16 Ahi[2][128 * 24], Alo[2][128 * 24];
    __shared__ __nv_bfloat16 Bhi[2][16 * 136], Blo[2][16 * 136];
    __shared__ int sidx[128], tidx[128], bidx[128];
    __shared__ float outs[128], b1s[128], W2s[128];

    int tid = threadIdx.x;
    int wid = tid >> 5, lane = tid & 31;
    int wm = (wid & 3) * 32, wn = (wid >> 2) * 64;
    int e0 = blockIdx.x * 128;

    if (tid < 128) {
        b1s[tid] = b1[tid];
        W2s[tid] = W2[tid];
        outs[tid] = 0.f;
        int e = e0 + tid;
        int s = 0, t = 0, b = 0;
        if (e < E) {
            s = __ldg(&ei[e]);
            t = __ldg(&ei[E + e]);
            b = __ldg(&batch[s]);
        }
        sidx[tid] = s; tidx[tid] = t; bidx[tid] = b;
    }

    float c[2][8][4];
#pragma unroll
    for (int mf = 0; mf < 2; ++mf)
#pragma unroll
        for (int nf = 0; nf < 8; ++nf)
#pragma unroll
            for (int q = 0; q < 4; ++q) c[mf][nf][q] = 0.f;

    int l15 = lane & 15, l16 = lane >> 4;
    unsigned aOff = ((wm + l15) * 24 + l16 * 8) * 2;
    unsigned bOff = (l15 * 136 + wn) * 2;

    int am = tid >> 1, half = tid & 1;
    int br = tid >> 4, bc = (tid & 15) * 8;

    const float* Aptr = ea + (size_t)(e0 + am) * 128 + half * 8;
    bool aValid = (e0 + am) < E;

    float4 v0 = make_float4(0.f, 0.f, 0.f, 0.f), v1 = v0;
    if (aValid) { v0 = *(const float4*)(Aptr); v1 = *(const float4*)(Aptr + 4); }
    uint4 bh = *(const uint4*)&g_BeHi[(size_t)br * 128 + bc];
    uint4 bl = *(const uint4*)&g_BeLo[(size_t)br * 128 + bc];
    {
        unsigned h01, l01, h23, l23, h45, l45, h67, l67;
        split2(v0.x, v0.y, h01, l01); split2(v0.z, v0.w, h23, l23);
        split2(v1.x, v1.y, h45, l45); split2(v1.z, v1.w, h67, l67);
        *(uint4*)&Ahi[0][am * 24 + half * 8] = make_uint4(h01, h23, h45, h67);
        *(uint4*)&Alo[0][am * 24 + half * 8] = make_uint4(l01, l23, l45, l67);
        *(uint4*)&Bhi[0][br * 136 + bc] = bh;
        *(uint4*)&Blo[0][br * 136 + bc] = bl;
    }
    __syncthreads();

    for (int kt = 0; kt < 8; ++kt) {
        int buf = kt & 1;
        if (kt + 1 < 8) {
            if (aValid) {
                const float* src = Aptr + (kt + 1) * 16;
                v0 = *(const float4*)(src);
                v1 = *(const float4*)(src + 4);
            }
            bh = *(const uint4*)&g_BeHi[(size_t)((kt + 1) * 16 + br) * 128 + bc];
            bl = *(const uint4*)&g_BeLo[(size_t)((kt + 1) * 16 + br) * 128 + bc];
        }

        unsigned ah[2][4], al[2][4];
        unsigned aBase = smem_u32(Ahi[buf]), aBaseL = smem_u32(Alo[buf]);
        ldsm4(aBase + aOff,            ah[0][0], ah[0][1], ah[0][2], ah[0][3]);
        ldsm4(aBase + aOff + 16 * 48,  ah[1][0], ah[1][1], ah[1][2], ah[1][3]);
        ldsm4(aBaseL + aOff,           al[0][0], al[0][1], al[0][2], al[0][3]);
        ldsm4(aBaseL + aOff + 16 * 48, al[1][0], al[1][1], al[1][2], al[1][3]);
        unsigned bBase = smem_u32(Bhi[buf]) + bOff, bBaseL = smem_u32(Blo[buf]) + bOff;
#pragma unroll
        for (int nf = 0; nf < 8; ++nf) {
            unsigned bhr[2], blr[2];
            ldsm2t(bBase + nf * 16, bhr[0], bhr[1]);
            ldsm2t(bBaseL + nf * 16, blr[0], blr[1]);
#pragma unroll
            for (int mf = 0; mf < 2; ++mf) {
                mma16816(c[mf][nf], ah[mf], bhr);
                mma16816(c[mf][nf], al[mf], bhr);
                mma16816(c[mf][nf], ah[mf], blr);
            }
        }

        if (kt + 1 < 8) {
            unsigned h01, l01, h23, l23, h45, l45, h67, l67;
            split2(v0.x, v0.y, h01, l01); split2(v0.z, v0.w, h23, l23);
            split2(v1.x, v1.y, h45, l45); split2(v1.z, v1.w, h67, l67);
            *(uint4*)&Ahi[buf ^ 1][am * 24 + half * 8] = make_uint4(h01, h23, h45, h67);
            *(uint4*)&Alo[buf ^ 1][am * 24 + half * 8] = make_uint4(l01, l23, l45, l67);
            *(uint4*)&Bhi[buf ^ 1][br * 136 + bc] = bh;
            *(uint4*)&Blo[buf ^ 1][br * 136 + bc] = bl;
        }
        __syncthreads();
    }

    // Epilogue: per-row gather + relu + W2 dot, reduce over n
    int r = lane >> 2, q = (lane & 3) * 2;
    float b2v = __ldg(b2);
#pragma unroll
    for (int mf = 0; mf < 2; ++mf) {
#pragma unroll
        for (int hf = 0; hf < 2; ++hf) {
            int row = wm + mf * 16 + hf * 8 + r;
            int s = sidx[row], t = tidx[row], b = bidx[row];
            const float* As = g_AB + (size_t)s * 256;
            const float* Bs = g_AB + (size_t)t * 256 + 128;
            const float* Ps = g_P + b * 128;
            float partial = 0.f;
#pragma unroll
            for (int nf = 0; nf < 8; ++nf) {
                int n = wn + nf * 8 + q;
                float2 a2 = *(const float2*)(As + n);
                float2 bb = *(const float2*)(Bs + n);
                float2 p2 = *(const float2*)(Ps + n);
                float c0 = c[mf][nf][hf * 2 + 0];
                float c1 = c[mf][nf][hf * 2 + 1];
                partial += fmaxf(c0 + a2.x + bb.x + p2.x + b1s[n], 0.f) * W2s[n]
                         + fmaxf(c1 + a2.y + bb.y + p2.y + b1s[n + 1], 0.f) * W2s[n + 1];
            }
            partial += __shfl_xor_sync(0xffffffffu, partial, 1);
            partial += __shfl_xor_sync(0xffffffffu, partial, 2);
            if ((lane & 3) == 0) atomicAdd(&outs[row], partial);
        }
    }
    __syncthreads();
    if (tid < 128) {
        int e = e0 + tid;
        if (e < E) out[e] = outs[tid] + b2v;
    }
}

// ---------------------------------------------------------------------------
extern "C" void kernel_launch(void* const* d_in, const int* in_sizes, int n_in,
                              void* d_out, int out_size) {
    const float* h     = (const float*)d_in[0];
    const int*   ei    = (const int*)d_in[1];     // int32 (JAX x64 disabled)
    const float* ea    = (const float*)d_in[2];
    const int*   batch = (const int*)d_in[3];     // int32
    const float* W1    = (const float*)d_in[4];
    const float* b1    = (const float*)d_in[5];
    const float* W2    = (const float*)d_in[6];
    const float* b2    = (const float*)d_in[7];
    float* out = (float*)d_out;

    int N = in_sizes[0] / ND;
    int E = in_sizes[2] / ED;

    prep_kernel<<<(256 * 256 + 255) / 256, 256>>>(W1);
    offsets_kernel<<<(NUM_GRAPHS + 256) / 256, 256>>>(batch, N);
    pool_kernel<<<NUM_GRAPHS, 128>>>(h, W1);

    float* AB = nullptr; cudaGetSymbolAddress((void**)&AB, g_AB);

    dim3 ngrid((N + 127) / 128, 2);
    node_gemm_bf16<<<ngrid, 256>>>(h, AB, N);

    int eblk = (E + 127) / 128;
    edge_gemm_fused<<<eblk, 256>>>(ea, ei, batch, b1, W2, b2, out, E);
}

// round 14
// speedup vs baseline: 2.5619x; 1.0127x over previous
#include <cuda_runtime.h>
#include <cuda_bf16.h>

#define NUM_GRAPHS 2048
#define ND 256
#define ED 128
#define HD 128
#define MAXN 100000

// Scratch (device globals: allocation-free per harness rules)
__device__ __align__(16) int   g_offsets[NUM_GRAPHS + 1];
__device__ __align__(16) float g_P[NUM_GRAPHS * HD];          // pooled @ W1d [2048,128]
__device__ __align__(16) float g_AB[(size_t)MAXN * 256];      // [h@W1a | h@W1b]
__device__ __align__(16) __nv_bfloat16 g_BnHi[256 * 256];     // [W1a|W1b] split, k-major
__device__ __align__(16) __nv_bfloat16 g_BnLo[256 * 256];
__device__ __align__(16) __nv_bfloat16 g_BeHi[128 * 128];     // W1c split, k-major
__device__ __align__(16) __nv_bfloat16 g_BeLo[128 * 128];

// ---------------------------------------------------------------------------
// mma/ldmatrix helpers
// ---------------------------------------------------------------------------
__device__ __forceinline__ unsigned smem_u32(const void* p) {
    return (unsigned)__cvta_generic_to_shared(p);
}
__device__ __forceinline__ void ldsm4(unsigned addr, unsigned& r0, unsigned& r1,
                                      unsigned& r2, unsigned& r3) {
    asm volatile("ldmatrix.sync.aligned.m8n8.x4.shared.b16 {%0,%1,%2,%3}, [%4];"
                 : "=r"(r0), "=r"(r1), "=r"(r2), "=r"(r3) : "r"(addr));
}
__device__ __forceinline__ void ldsm4t(unsigned addr, unsigned& r0, unsigned& r1,
                                       unsigned& r2, unsigned& r3) {
    asm volatile("ldmatrix.sync.aligned.m8n8.x4.trans.shared.b16 {%0,%1,%2,%3}, [%4];"
                 : "=r"(r0), "=r"(r1), "=r"(r2), "=r"(r3) : "r"(addr));
}
__device__ __forceinline__ void mma16816(float* c, const unsigned* a, const unsigned* b) {
    asm volatile("mma.sync.aligned.m16n8k16.row.col.f32.bf16.bf16.f32 "
                 "{%0,%1,%2,%3}, {%4,%5,%6,%7}, {%8,%9}, {%0,%1,%2,%3};"
                 : "+f"(c[0]), "+f"(c[1]), "+f"(c[2]), "+f"(c[3])
                 : "r"(a[0]), "r"(a[1]), "r"(a[2]), "r"(a[3]), "r"(b[0]), "r"(b[1]));
}
__device__ __forceinline__ void split2(float x0, float x1, unsigned& hi, unsigned& lo) {
    __nv_bfloat16 h0 = __float2bfloat16(x0), h1 = __float2bfloat16(x1);
    __nv_bfloat16 l0 = __float2bfloat16(x0 - __bfloat162float(h0));
    __nv_bfloat16 l1 = __float2bfloat16(x1 - __bfloat162float(h1));
    __nv_bfloat162 H = __nv_bfloat162(h0, h1), L = __nv_bfloat162(l0, l1);
    hi = *(unsigned*)&H;
    lo = *(unsigned*)&L;
}

// ---------------------------------------------------------------------------
// Kernel 0: split weights into bf16 hi/lo (k-major)
// ---------------------------------------------------------------------------
__global__ void prep_kernel(const float* __restrict__ W1) {
    int idx = blockIdx.x * blockDim.x + threadIdx.x;
    if (idx < 256 * 256) {
        int k = idx >> 8, n = idx & 255;
        float w = (n < 128) ? W1[(size_t)k * 128 + n]
                            : W1[(size_t)(256 + k) * 128 + (n - 128)];
        __nv_bfloat16 hi = __float2bfloat16(w);
        g_BnHi[idx] = hi;
        g_BnLo[idx] = __float2bfloat16(w - __bfloat162float(hi));
    }
    if (idx < 128 * 128) {
        int k = idx >> 7, n = idx & 127;
        float w = W1[(size_t)(512 + k) * 128 + n];
        __nv_bfloat16 hi = __float2bfloat16(w);
        g_BeHi[idx] = hi;
        g_BeLo[idx] = __float2bfloat16(w - __bfloat162float(hi));
    }
}

// ---------------------------------------------------------------------------
// Kernel 1: graph start offsets via binary search (batch is sorted int32)
// ---------------------------------------------------------------------------
__global__ void offsets_kernel(const int* __restrict__ batch, int N) {
    int g = blockIdx.x * blockDim.x + threadIdx.x;
    if (g > NUM_GRAPHS) return;
    int lo = 0, hi = N;
    while (lo < hi) {
        int mid = (lo + hi) >> 1;
        if (batch[mid] < g) lo = mid + 1; else hi = mid;
    }
    g_offsets[g] = lo;
}

// ---------------------------------------------------------------------------
// Kernel 2: per-graph mean pooling + P = pooled @ W1d (W1 rows 640..895)
// ---------------------------------------------------------------------------
__global__ void pool_kernel(const float* __restrict__ h, const float* __restrict__ W1) {
    __shared__ float pool_s[ND];
    int g = blockIdx.x;
    int tid = threadIdx.x;
    int o0 = g_offsets[g], o1 = g_offsets[g + 1];
    float s0 = 0.f, s1 = 0.f;
    int r = o0;
    for (; r + 1 < o1; r += 2) {
        const float* row0 = h + (size_t)r * ND;
        const float* row1 = row0 + ND;
        s0 += row0[tid] + row1[tid];
        s1 += row0[tid + 128] + row1[tid + 128];
    }
    if (r < o1) {
        const float* row = h + (size_t)r * ND;
        s0 += row[tid];
        s1 += row[tid + 128];
    }
    int cnt = o1 - o0;
    float inv = 1.f / (float)(cnt > 1 ? cnt : 1);
    pool_s[tid]       = s0 * inv;
    pool_s[tid + 128] = s1 * inv;
    __syncthreads();
    float acc = 0.f;
    const float* Wg = W1 + (size_t)640 * HD;
#pragma unroll 8
    for (int k = 0; k < ND; ++k) acc += pool_s[k] * Wg[k * HD + tid];
    g_P[g * HD + tid] = acc;
}

// ---------------------------------------------------------------------------
// Kernel 3: node GEMM (double-buffered, reg-prefetch, one sync/k-tile).
// block tile 128m x 128n (grid.y selects AB half), 256 thr = 8 warps (4m x 2n).
// B fragments via ldmatrix.x4.trans (16k x 16n per instruction).
// ---------------------------------------------------------------------------
__global__ __launch_bounds__(256, 2) void node_gemm_bf16(const float* __restrict__ h,
                                                         float* __restrict__ AB, int M) {
    __shared__ __nv_bfloat16 Ahi[2][128 * 24], Alo[2][128 * 24];
    __shared__ __nv_bfloat16 Bhi[2][16 * 136], Blo[2][16 * 136];

    int tid = threadIdx.x;
    int wid = tid >> 5, lane = tid & 31;
    int wm = (wid & 3) * 32, wn = (wid >> 2) * 64;
    int m0 = blockIdx.x * 128;
    int nb = blockIdx.y * 128;
    const __nv_bfloat16* BHi = g_BnHi + nb;
    const __nv_bfloat16* BLo = g_BnLo + nb;

    float c[2][8][4];
#pragma unroll
    for (int mf = 0; mf < 2; ++mf)
#pragma unroll
        for (int nf = 0; nf < 8; ++nf)
#pragma unroll
            for (int q = 0; q < 4; ++q) c[mf][nf][q] = 0.f;

    int l15 = lane & 15, l16 = lane >> 4;
    unsigned aOff = ((wm + l15) * 24 + l16 * 8) * 2;
    // x4.trans B: lanes 0-15 -> 16 k-rows, lane>>4 -> n column-half (+8)
    unsigned bOff = (l15 * 136 + wn + l16 * 8) * 2;

    int am = tid >> 1, half = tid & 1;         // A loader: 8 floats
    int br = tid >> 4, bc = (tid & 15) * 8;    // B loader

    const float* Aptr = h + (size_t)(m0 + am) * 256 + half * 8;
    bool aValid = (m0 + am) < M;

    float4 v0 = make_float4(0.f, 0.f, 0.f, 0.f), v1 = v0;
    if (aValid) { v0 = *(const float4*)(Aptr); v1 = *(const float4*)(Aptr + 4); }
    uint4 bh = *(const uint4*)&BHi[(size_t)br * 256 + bc];
    uint4 bl = *(const uint4*)&BLo[(size_t)br * 256 + bc];
    {
        unsigned h01, l01, h23, l23, h45, l45, h67, l67;
        split2(v0.x, v0.y, h01, l01); split2(v0.z, v0.w, h23, l23);
        split2(v1.x, v1.y, h45, l45); split2(v1.z, v1.w, h67, l67);
        *(uint4*)&Ahi[0][am * 24 + half * 8] = make_uint4(h01, h23, h45, h67);
        *(uint4*)&Alo[0][am * 24 + half * 8] = make_uint4(l01, l23, l45, l67);
        *(uint4*)&Bhi[0][br * 136 + bc] = bh;
        *(uint4*)&Blo[0][br * 136 + bc] = bl;
    }
    __syncthreads();

    for (int kt = 0; kt < 16; ++kt) {
        int buf = kt & 1;
        if (kt + 1 < 16) {
            if (aValid) {
                const float* src = Aptr + (kt + 1) * 16;
                v0 = *(const float4*)(src);
                v1 = *(const float4*)(src + 4);
            }
            bh = *(const uint4*)&BHi[(size_t)((kt + 1) * 16 + br) * 256 + bc];
            bl = *(const uint4*)&BLo[(size_t)((kt + 1) * 16 + br) * 256 + bc];
        }

        unsigned ah[2][4], al[2][4];
        unsigned aBase = smem_u32(Ahi[buf]), aBaseL = smem_u32(Alo[buf]);
        ldsm4(aBase + aOff,            ah[0][0], ah[0][1], ah[0][2], ah[0][3]);
        ldsm4(aBase + aOff + 16 * 48,  ah[1][0], ah[1][1], ah[1][2], ah[1][3]);
        ldsm4(aBaseL + aOff,           al[0][0], al[0][1], al[0][2], al[0][3]);
        ldsm4(aBaseL + aOff + 16 * 48, al[1][0], al[1][1], al[1][2], al[1][3]);
        unsigned bBase = smem_u32(Bhi[buf]) + bOff, bBaseL = smem_u32(Blo[buf]) + bOff;
#pragma unroll
        for (int nf2 = 0; nf2 < 4; ++nf2) {
            unsigned bhr[4], blr[4];
            ldsm4t(bBase + nf2 * 32, bhr[0], bhr[1], bhr[2], bhr[3]);
            ldsm4t(bBaseL + nf2 * 32, blr[0], blr[1], blr[2], blr[3]);
#pragma unroll
            for (int mf = 0; mf < 2; ++mf) {
                mma16816(c[mf][2 * nf2],     ah[mf], bhr);
                mma16816(c[mf][2 * nf2],     al[mf], bhr);
                mma16816(c[mf][2 * nf2],     ah[mf], blr);
                mma16816(c[mf][2 * nf2 + 1], ah[mf], bhr + 2);
                mma16816(c[mf][2 * nf2 + 1], al[mf], bhr + 2);
                mma16816(c[mf][2 * nf2 + 1], ah[mf], blr + 2);
            }
        }

        if (kt + 1 < 16) {
            unsigned h01, l01, h23, l23, h45, l45, h67, l67;
            split2(v0.x, v0.y, h01, l01); split2(v0.z, v0.w, h23, l23);
            split2(v1.x, v1.y, h45, l45); split2(v1.z, v1.w, h67, l67);
            *(uint4*)&Ahi[buf ^ 1][am * 24 + half * 8] = make_uint4(h01, h23, h45, h67);
            *(uint4*)&Alo[buf ^ 1][am * 24 + half * 8] = make_uint4(l01, l23, l45, l67);
            *(uint4*)&Bhi[buf ^ 1][br * 136 + bc] = bh;
            *(uint4*)&Blo[buf ^ 1][br * 136 + bc] = bl;
        }
        __syncthreads();
    }

    int r = lane >> 2, q = (lane & 3) * 2;
#pragma unroll
    for (int mf = 0; mf < 2; ++mf)
#pragma unroll
        for (int nf = 0; nf < 8; ++nf) {
            int m = m0 + wm + mf * 16 + r;
            int n = nb + wn + nf * 8 + q;
            if (m < M)
                *(float2*)&AB[(size_t)m * 256 + n] = make_float2(c[mf][nf][0], c[mf][nf][1]);
            if (m + 8 < M)
                *(float2*)&AB[(size_t)(m + 8) * 256 + n] = make_float2(c[mf][nf][2], c[mf][nf][3]);
        }
}

// ---------------------------------------------------------------------------
// Kernel 4: fused edge GEMM (same pipeline, x4t B loads) + epilogue.
// ---------------------------------------------------------------------------
__global__ __launch_bounds__(256, 2) void edge_gemm_fused(const float* __restrict__ ea,
                                                          const int* __restrict__ ei,
                                                          const int* __restrict__ batch,
                                                          const float* __restrict__ b1,
                                                          const float* __restrict__ W2,
                                                          const float* __restrict__ b2,
                                                          float* __restrict__ out, int E) {
    __shared__ __nv_bfloat16 Ahi[2][128 * 24], Alo[2][128 * 24];
    __shared__ __nv_bfloat16 Bhi[2][16 * 136], Blo[2][16 * 136];
    __shared__ int sidx[128], tidx[128], bidx[128];
    __shared__ float outs[128], b1s[128], W2s[128];

    int tid = threadIdx.x;
    int wid = tid >> 5, lane = tid & 31;
    int wm = (wid & 3) * 32, wn = (wid >> 2) * 64;
    int e0 = blockIdx.x * 128;

    if (tid < 128) {
        b1s[tid] = b1[tid];
        W2s[tid] = W2[tid];
        outs[tid] = 0.f;
        int e = e0 + tid;
        int s = 0, t = 0, b = 0;
        if (e < E) {
            s = __ldg(&ei[e]);
            t = __ldg(&ei[E + e]);
            b = __ldg(&batch[s]);
        }
        sidx[tid] = s; tidx[tid] = t; bidx[tid] = b;
    }

    float c[2][8][4];
#pragma unroll
    for (int mf = 0; mf < 2; ++mf)
#pragma unroll
        for (int nf = 0; nf < 8; ++nf)
#pragma unroll
            for (int q = 0; q < 4; ++q) c[mf][nf][q] = 0.f;

    int l15 = lane & 15, l16 = lane >> 4;
    unsigned aOff = ((wm + l15) * 24 + l16 * 8) * 2;
    unsigned bOff = (l15 * 136 + wn + l16 * 8) * 2;

    int am = tid >> 1, half = tid & 1;
    int br = tid >> 4, bc = (tid & 15) * 8;

    const float* Aptr = ea + (size_t)(e0 + am) * 128 + half * 8;
    bool aValid = (e0 + am) < E;

    float4 v0 = make_float4(0.f, 0.f, 0.f, 0.f), v1 = v0;
    if (aValid) { v0 = *(const float4*)(Aptr); v1 = *(const float4*)(Aptr + 4); }
    uint4 bh = *(const uint4*)&g_BeHi[(size_t)br * 128 + bc];
    uint4 bl = *(const uint4*)&g_BeLo[(size_t)br * 128 + bc];
    {
        unsigned h01, l01, h23, l23, h45, l45, h67, l67;
        split2(v0.x, v0.y, h01, l01); split2(v0.z, v0.w, h23, l23);
        split2(v1.x, v1.y, h45, l45); split2(v1.z, v1.w, h67, l67);
        *(uint4*)&Ahi[0][am * 24 + half * 8] = make_uint4(h01, h23, h45, h67);
        *(uint4*)&Alo[0][am * 24 + half * 8] = make_uint4(l01, l23, l45, l67);
        *(uint4*)&Bhi[0][br * 136 + bc] = bh;
        *(uint4*)&Blo[0][br * 136 + bc] = bl;
    }
    __syncthreads();

    for (int kt = 0; kt < 8; ++kt) {
        int buf = kt & 1;
        if (kt + 1 < 8) {
            if (aValid) {
                const float* src = Aptr + (kt + 1) * 16;
                v0 = *(const float4*)(src);
                v1 = *(const float4*)(src + 4);
            }
            bh = *(const uint4*)&g_BeHi[(size_t)((kt + 1) * 16 + br) * 128 + bc];
            bl = *(const uint4*)&g_BeLo[(size_t)((kt + 1) * 16 + br) * 128 + bc];
        }

        unsigned ah[2][4], al[2][4];
        unsigned aBase = smem_u32(Ahi[buf]), aBaseL = smem_u32(Alo[buf]);
        ldsm4(aBase + aOff,            ah[0][0], ah[0][1], ah[0][2], ah[0][3]);
        ldsm4(aBase + aOff + 16 * 48,  ah[1][0], ah[1][1], ah[1][2], ah[1][3]);
        ldsm4(aBaseL + aOff,           al[0][0], al[0][1], al[0][2], al[0][3]);
        ldsm4(aBaseL + aOff + 16 * 48, al[1][0], al[1][1], al[1][2], al[1][3]);
        unsigned bBase = smem_u32(Bhi[buf]) + bOff, bBaseL = smem_u32(Blo[buf]) + bOff;
#pragma unroll
        for (int nf2 = 0; nf2 < 4; ++nf2) {
            unsigned bhr[4], blr[4];
            ldsm4t(bBase + nf2 * 32, bhr[0], bhr[1], bhr[2], bhr[3]);
            ldsm4t(bBaseL + nf2 * 32, blr[0], blr[1], blr[2], blr[3]);
#pragma unroll
            for (int mf = 0; mf < 2; ++mf) {
                mma16816(c[mf][2 * nf2],     ah[mf], bhr);
                mma16816(c[mf][2 * nf2],     al[mf], bhr);
                mma16816(c[mf][2 * nf2],     ah[mf], blr);
                mma16816(c[mf][2 * nf2 + 1], ah[mf], bhr + 2);
                mma16816(c[mf][2 * nf2 + 1], al[mf], bhr + 2);
                mma16816(c[mf][2 * nf2 + 1], ah[mf], blr + 2);
            }
        }

        if (kt + 1 < 8) {
            unsigned h01, l01, h23, l23, h45, l45, h67, l67;
            split2(v0.x, v0.y, h01, l01); split2(v0.z, v0.w, h23, l23);
            split2(v1.x, v1.y, h45, l45); split2(v1.z, v1.w, h67, l67);
            *(uint4*)&Ahi[buf ^ 1][am * 24 + half * 8] = make_uint4(h01, h23, h45, h67);
            *(uint4*)&Alo[buf ^ 1][am * 24 + half * 8] = make_uint4(l01, l23, l45, l67);
            *(uint4*)&Bhi[buf ^ 1][br * 136 + bc] = bh;
            *(uint4*)&Blo[buf ^ 1][br * 136 + bc] = bl;
        }
        __syncthreads();
    }

    // Epilogue: per-row gather + relu + W2 dot, reduce over n
    int r = lane >> 2, q = (lane & 3) * 2;
    float b2v = __ldg(b2);
#pragma unroll
    for (int mf = 0; mf < 2; ++mf) {
#pragma unroll
        for (int hf = 0; hf < 2; ++hf) {
            int row = wm + mf * 16 + hf * 8 + r;
            int s = sidx[row], t = tidx[row], b = bidx[row];
            const float* As = g_AB + (size_t)s * 256;
            const float* Bs = g_AB + (size_t)t * 256 + 128;
            const float* Ps = g_P + b * 128;
            float partial = 0.f;
#pragma unroll
            for (int nf = 0; nf < 8; ++nf) {
                int n = wn + nf * 8 + q;
                float2 a2 = *(const float2*)(As + n);
                float2 bb = *(const float2*)(Bs + n);
                float2 p2 = *(const float2*)(Ps + n);
                float c0 = c[mf][nf][hf * 2 + 0];
                float c1 = c[mf][nf][hf * 2 + 1];
                partial += fmaxf(c0 + a2.x + bb.x + p2.x + b1s[n], 0.f) * W2s[n]
                         + fmaxf(c1 + a2.y + bb.y + p2.y + b1s[n + 1], 0.f) * W2s[n + 1];
            }
            partial += __shfl_xor_sync(0xffffffffu, partial, 1);
            partial += __shfl_xor_sync(0xffffffffu, partial, 2);
            if ((lane & 3) == 0) atomicAdd(&outs[row], partial);
        }
    }
    __syncthreads();
    if (tid < 128) {
        int e = e0 + tid;
        if (e < E) out[e] = outs[tid] + b2v;
    }
}

// ---------------------------------------------------------------------------
extern "C" void kernel_launch(void* const* d_in, const int* in_sizes, int n_in,
                              void* d_out, int out_size) {
    const float* h     = (const float*)d_in[0];
    const int*   ei    = (const int*)d_in[1];     // int32 (JAX x64 disabled)
    const float* ea    = (const float*)d_in[2];
    const int*   batch = (const int*)d_in[3];     // int32
    const float* W1    = (const float*)d_in[4];
    const float* b1    = (const float*)d_in[5];
    const float* W2    = (const float*)d_in[6];
    const float* b2    = (const float*)d_in[7];
    float* out = (float*)d_out;

    int N = in_sizes[0] / ND;
    int E = in_sizes[2] / ED;

    prep_kernel<<<(256 * 256 + 255) / 256, 256>>>(W1);
    offsets_kernel<<<(NUM_GRAPHS + 256) / 256, 256>>>(batch, N);
    pool_kernel<<<NUM_GRAPHS, 128>>>(h, W1);

    float* AB = nullptr; cudaGetSymbolAddress((void**)&AB, g_AB);

    dim3 ngrid((N + 127) / 128, 2);
    node_gemm_bf16<<<ngrid, 256>>>(h, AB, N);

    int eblk = (E + 127) / 128;
    edge_gemm_fused<<<eblk, 256>>>(ea, ei, batch, b1, W2, b2, out, E);
}

// round 15
// speedup vs baseline: 2.8349x; 1.1066x over previous
#include <cuda_runtime.h>
#include <cuda_fp16.h>

#define NUM_GRAPHS 2048
#define ND 256
#define ED 128
#define HD 128
#define MAXN 100000

// Scratch (device globals: allocation-free per harness rules)
__device__ __align__(16) int   g_offsets[NUM_GRAPHS + 1];
__device__ __align__(16) float g_P[NUM_GRAPHS * HD];          // pooled @ W1d [2048,128]
__device__ __align__(16) float g_AB[(size_t)MAXN * 256];      // [h@W1a | h@W1b]
__device__ __align__(16) __half g_Bn[256 * 256];              // [W1a|W1b] fp16, k-major
__device__ __align__(16) __half g_Be[128 * 128];              // W1c fp16, k-major

// ---------------------------------------------------------------------------
// mma/ldmatrix helpers
// ---------------------------------------------------------------------------
__device__ __forceinline__ unsigned smem_u32(const void* p) {
    return (unsigned)__cvta_generic_to_shared(p);
}
__device__ __forceinline__ void ldsm4(unsigned addr, unsigned& r0, unsigned& r1,
                                      unsigned& r2, unsigned& r3) {
    asm volatile("ldmatrix.sync.aligned.m8n8.x4.shared.b16 {%0,%1,%2,%3}, [%4];"
                 : "=r"(r0), "=r"(r1), "=r"(r2), "=r"(r3) : "r"(addr));
}
__device__ __forceinline__ void ldsm4t(unsigned addr, unsigned& r0, unsigned& r1,
                                       unsigned& r2, unsigned& r3) {
    asm volatile("ldmatrix.sync.aligned.m8n8.x4.trans.shared.b16 {%0,%1,%2,%3}, [%4];"
                 : "=r"(r0), "=r"(r1), "=r"(r2), "=r"(r3) : "r"(addr));
}
__device__ __forceinline__ void mma16816(float* c, const unsigned* a, const unsigned* b) {
    asm volatile("mma.sync.aligned.m16n8k16.row.col.f32.f16.f16.f32 "
                 "{%0,%1,%2,%3}, {%4,%5,%6,%7}, {%8,%9}, {%0,%1,%2,%3};"
                 : "+f"(c[0]), "+f"(c[1]), "+f"(c[2]), "+f"(c[3])
                 : "r"(a[0]), "r"(a[1]), "r"(a[2]), "r"(a[3]), "r"(b[0]), "r"(b[1]));
}
// fp16 hi/lo split of two fp32 values -> packed half2 regs
__device__ __forceinline__ void split2h(float x0, float x1, unsigned& hi, unsigned& lo) {
    __half h0 = __float2half_rn(x0), h1 = __float2half_rn(x1);
    __half l0 = __float2half_rn(x0 - __half2float(h0));
    __half l1 = __float2half_rn(x1 - __half2float(h1));
    __half2 H = __halves2half2(h0, h1), L = __halves2half2(l0, l1);
    hi = *(unsigned*)&H;
    lo = *(unsigned*)&L;
}

// ---------------------------------------------------------------------------
// Kernel 0: weights -> fp16, k-major
// ---------------------------------------------------------------------------
__global__ void prep_kernel(const float* __restrict__ W1) {
    int idx = blockIdx.x * blockDim.x + threadIdx.x;
    if (idx < 256 * 256) {
        int k = idx >> 8, n = idx & 255;
        float w = (n < 128) ? W1[(size_t)k * 128 + n]
                            : W1[(size_t)(256 + k) * 128 + (n - 128)];
        g_Bn[idx] = __float2half_rn(w);
    }
    if (idx < 128 * 128) {
        int k = idx >> 7, n = idx & 127;
        g_Be[idx] = __float2half_rn(W1[(size_t)(512 + k) * 128 + n]);
    }
}

// ---------------------------------------------------------------------------
// Kernel 1: graph start offsets via binary search (batch is sorted int32)
// ---------------------------------------------------------------------------
__global__ void offsets_kernel(const int* __restrict__ batch, int N) {
    int g = blockIdx.x * blockDim.x + threadIdx.x;
    if (g > NUM_GRAPHS) return;
    int lo = 0, hi = N;
    while (lo < hi) {
        int mid = (lo + hi) >> 1;
        if (batch[mid] < g) lo = mid + 1; else hi = mid;
    }
    g_offsets[g] = lo;
}

// ---------------------------------------------------------------------------
// Kernel 2: per-graph mean pooling + P = pooled @ W1d (W1 rows 640..895)
// ---------------------------------------------------------------------------
__global__ void pool_kernel(const float* __restrict__ h, const float* __restrict__ W1) {
    __shared__ float pool_s[ND];
    int g = blockIdx.x;
    int tid = threadIdx.x;
    int o0 = g_offsets[g], o1 = g_offsets[g + 1];
    float s0 = 0.f, s1 = 0.f;
    int r = o0;
    for (; r + 1 < o1; r += 2) {
        const float* row0 = h + (size_t)r * ND;
        const float* row1 = row0 + ND;
        s0 += row0[tid] + row1[tid];
        s1 += row0[tid + 128] + row1[tid + 128];
    }
    if (r < o1) {
        const float* row = h + (size_t)r * ND;
        s0 += row[tid];
        s1 += row[tid + 128];
    }
    int cnt = o1 - o0;
    float inv = 1.f / (float)(cnt > 1 ? cnt : 1);
    pool_s[tid]       = s0 * inv;
    pool_s[tid + 128] = s1 * inv;
    __syncthreads();
    float acc = 0.f;
    const float* Wg = W1 + (size_t)640 * HD;
#pragma unroll 8
    for (int k = 0; k < ND; ++k) acc += pool_s[k] * Wg[k * HD + tid];
    g_P[g * HD + tid] = acc;
}

// ---------------------------------------------------------------------------
// Kernel 3: node GEMM, fp16 2-term split (A=hi+lo, B=fp16).
// block tile 128m x 128n (grid.y selects AB half), 256 thr = 8 warps (4m x 2n).
// Double-buffered, reg-prefetch, one sync per k-tile.
// ---------------------------------------------------------------------------
__global__ __launch_bounds__(256, 2) void node_gemm_fp16(const float* __restrict__ h,
                                                         float* __restrict__ AB, int M) {
    __shared__ __half Ahi[2][128 * 24], Alo[2][128 * 24];
    __shared__ __half Bs[2][16 * 136];

    int tid = threadIdx.x;
    int wid = tid >> 5, lane = tid & 31;
    int wm = (wid & 3) * 32, wn = (wid >> 2) * 64;
    int m0 = blockIdx.x * 128;
    int nb = blockIdx.y * 128;
    const __half* Bg = g_Bn + nb;

    float c[2][8][4];
#pragma unroll
    for (int mf = 0; mf < 2; ++mf)
#pragma unroll
        for (int nf = 0; nf < 8; ++nf)
#pragma unroll
            for (int q = 0; q < 4; ++q) c[mf][nf][q] = 0.f;

    int l15 = lane & 15, l16 = lane >> 4;
    unsigned aOff = ((wm + l15) * 24 + l16 * 8) * 2;
    unsigned bOff = (l15 * 136 + wn + l16 * 8) * 2;

    int am = tid >> 1, half = tid & 1;         // A loader: 8 floats
    int br = tid >> 4, bc = (tid & 15) * 8;    // B loader: 8 fp16

    const float* Aptr = h + (size_t)(m0 + am) * 256 + half * 8;
    bool aValid = (m0 + am) < M;

    float4 v0 = make_float4(0.f, 0.f, 0.f, 0.f), v1 = v0;
    if (aValid) { v0 = *(const float4*)(Aptr); v1 = *(const float4*)(Aptr + 4); }
    uint4 bv = *(const uint4*)&Bg[(size_t)br * 256 + bc];
    {
        unsigned h01, l01, h23, l23, h45, l45, h67, l67;
        split2h(v0.x, v0.y, h01, l01); split2h(v0.z, v0.w, h23, l23);
        split2h(v1.x, v1.y, h45, l45); split2h(v1.z, v1.w, h67, l67);
        *(uint4*)&Ahi[0][am * 24 + half * 8] = make_uint4(h01, h23, h45, h67);
        *(uint4*)&Alo[0][am * 24 + half * 8] = make_uint4(l01, l23, l45, l67);
        *(uint4*)&Bs[0][br * 136 + bc] = bv;
    }
    __syncthreads();

    for (int kt = 0; kt < 16; ++kt) {
        int buf = kt & 1;
        if (kt + 1 < 16) {
            if (aValid) {
                const float* src = Aptr + (kt + 1) * 16;
                v0 = *(const float4*)(src);
                v1 = *(const float4*)(src + 4);
            }
            bv = *(const uint4*)&Bg[(size_t)((kt + 1) * 16 + br) * 256 + bc];
        }

        unsigned ah[2][4], al[2][4];
        unsigned aBase = smem_u32(Ahi[buf]), aBaseL = smem_u32(Alo[buf]);
        ldsm4(aBase + aOff,            ah[0][0], ah[0][1], ah[0][2], ah[0][3]);
        ldsm4(aBase + aOff + 16 * 48,  ah[1][0], ah[1][1], ah[1][2], ah[1][3]);
        ldsm4(aBaseL + aOff,           al[0][0], al[0][1], al[0][2], al[0][3]);
        ldsm4(aBaseL + aOff + 16 * 48, al[1][0], al[1][1], al[1][2], al[1][3]);
        unsigned bBase = smem_u32(Bs[buf]) + bOff;
#pragma unroll
        for (int nf2 = 0; nf2 < 4; ++nf2) {
            unsigned b4[4];
            ldsm4t(bBase + nf2 * 32, b4[0], b4[1], b4[2], b4[3]);
#pragma unroll
            for (int mf = 0; mf < 2; ++mf) {
                mma16816(c[mf][2 * nf2],     ah[mf], b4);
                mma16816(c[mf][2 * nf2],     al[mf], b4);
                mma16816(c[mf][2 * nf2 + 1], ah[mf], b4 + 2);
                mma16816(c[mf][2 * nf2 + 1], al[mf], b4 + 2);
            }
        }

        if (kt + 1 < 16) {
            unsigned h01, l01, h23, l23, h45, l45, h67, l67;
            split2h(v0.x, v0.y, h01, l01); split2h(v0.z, v0.w, h23, l23);
            split2h(v1.x, v1.y, h45, l45); split2h(v1.z, v1.w, h67, l67);
            *(uint4*)&Ahi[buf ^ 1][am * 24 + half * 8] = make_uint4(h01, h23, h45, h67);
            *(uint4*)&Alo[buf ^ 1][am * 24 + half * 8] = make_uint4(l01, l23, l45, l67);
            *(uint4*)&Bs[buf ^ 1][br * 136 + bc] = bv;
        }
        __syncthreads();
    }

    int r = lane >> 2, q = (lane & 3) * 2;
#pragma unroll
    for (int mf = 0; mf < 2; ++mf)
#pragma unroll
        for (int nf = 0; nf < 8; ++nf) {
            int m = m0 + wm + mf * 16 + r;
            int n = nb + wn + nf * 8 + q;
            if (m < M)
                *(float2*)&AB[(size_t)m * 256 + n] = make_float2(c[mf][nf][0], c[mf][nf][1]);
            if (m + 8 < M)
                *(float2*)&AB[(size_t)(m + 8) * 256 + n] = make_float2(c[mf][nf][2], c[mf][nf][3]);
        }
}

// ---------------------------------------------------------------------------
// Kernel 4: fused edge GEMM (fp16 2-term) + epilogue.
// ---------------------------------------------------------------------------
__global__ __launch_bounds__(256, 2) void edge_gemm_fused(const float* __restrict__ ea,
                                                          const int* __restrict__ ei,
                                                          const int* __restrict__ batch,
                                                          const float* __restrict__ b1,
                                                          const float* __restrict__ W2,
                                                          const float* __restrict__ b2,
                                                          float* __restrict__ out, int E) {
    __shared__ __half Ahi[2][128 * 24], Alo[2][128 * 24];
    __shared__ __half Bs[2][16 * 136];
    __shared__ int sidx[128], tidx[128], bidx[128];
    __shared__ float outs[128], b1s[128], W2s[128];

    int tid = threadIdx.x;
    int wid = tid >> 5, lane = tid & 31;
    int wm = (wid & 3) * 32, wn = (wid >> 2) * 64;
    int e0 = blockIdx.x * 128;

    if (tid < 128) {
        b1s[tid] = b1[tid];
        W2s[tid] = W2[tid];
        outs[tid] = 0.f;
        int e = e0 + tid;
        int s = 0, t = 0, b = 0;
        if (e < E) {
            s = __ldg(&ei[e]);
            t = __ldg(&ei[E + e]);
            b = __ldg(&batch[s]);
        }
        sidx[tid] = s; tidx[tid] = t; bidx[tid] = b;
    }

    float c[2][8][4];
#pragma unroll
    for (int mf = 0; mf < 2; ++mf)
#pragma unroll
        for (int nf = 0; nf < 8; ++nf)
#pragma unroll
            for (int q = 0; q < 4; ++q) c[mf][nf][q] = 0.f;

    int l15 = lane & 15, l16 = lane >> 4;
    unsigned aOff = ((wm + l15) * 24 + l16 * 8) * 2;
    unsigned bOff = (l15 * 136 + wn + l16 * 8) * 2;

    int am = tid >> 1, half = tid & 1;
    int br = tid >> 4, bc = (tid & 15) * 8;

    const float* Aptr = ea + (size_t)(e0 + am) * 128 + half * 8;
    bool aValid = (e0 + am) < E;

    float4 v0 = make_float4(0.f, 0.f, 0.f, 0.f), v1 = v0;
    if (aValid) { v0 = *(const float4*)(Aptr); v1 = *(const float4*)(Aptr + 4); }
    uint4 bv = *(const uint4*)&g_Be[(size_t)br * 128 + bc];
    {
        unsigned h01, l01, h23, l23, h45, l45, h67, l67;
        split2h(v0.x, v0.y, h01, l01); split2h(v0.z, v0.w, h23, l23);
        split2h(v1.x, v1.y, h45, l45); split2h(v1.z, v1.w, h67, l67);
        *(uint4*)&Ahi[0][am * 24 + half * 8] = make_uint4(h01, h23, h45, h67);
        *(uint4*)&Alo[0][am * 24 + half * 8] = make_uint4(l01, l23, l45, l67);
        *(uint4*)&Bs[0][br * 136 + bc] = bv;
    }
    __syncthreads();

    for (int kt = 0; kt < 8; ++kt) {
        int buf = kt & 1;
        if (kt + 1 < 8) {
            if (aValid) {
                const float* src = Aptr + (kt + 1) * 16;
                v0 = *(const float4*)(src);
                v1 = *(const float4*)(src + 4);
            }
            bv = *(const uint4*)&g_Be[(size_t)((kt + 1) * 16 + br) * 128 + bc];
        }

        unsigned ah[2][4], al[2][4];
        unsigned aBase = smem_u32(Ahi[buf]), aBaseL = smem_u32(Alo[buf]);
        ldsm4(aBase + aOff,            ah[0][0], ah[0][1], ah[0][2], ah[0][3]);
        ldsm4(aBase + aOff + 16 * 48,  ah[1][0], ah[1][1], ah[1][2], ah[1][3]);
        ldsm4(aBaseL + aOff,           al[0][0], al[0][1], al[0][2], al[0][3]);
        ldsm4(aBaseL + aOff + 16 * 48, al[1][0], al[1][1], al[1][2], al[1][3]);
        unsigned bBase = smem_u32(Bs[buf]) + bOff;
#pragma unroll
        for (int nf2 = 0; nf2 < 4; ++nf2) {
            unsigned b4[4];
            ldsm4t(bBase + nf2 * 32, b4[0], b4[1], b4[2], b4[3]);
#pragma unroll
            for (int mf = 0; mf < 2; ++mf) {
                mma16816(c[mf][2 * nf2],     ah[mf], b4);
                mma16816(c[mf][2 * nf2],     al[mf], b4);
                mma16816(c[mf][2 * nf2 + 1], ah[mf], b4 + 2);
                mma16816(c[mf][2 * nf2 + 1], al[mf], b4 + 2);
            }
        }

        if (kt + 1 < 8) {
            unsigned h01, l01, h23, l23, h45, l45, h67, l67;
            split2h(v0.x, v0.y, h01, l01); split2h(v0.z, v0.w, h23, l23);
            split2h(v1.x, v1.y, h45, l45); split2h(v1.z, v1.w, h67, l67);
            *(uint4*)&Ahi[buf ^ 1][am * 24 + half * 8] = make_uint4(h01, h23, h45, h67);
            *(uint4*)&Alo[buf ^ 1][am * 24 + half * 8] = make_uint4(l01, l23, l45, l67);
            *(uint4*)&Bs[buf ^ 1][br * 136 + bc] = bv;
        }
        __syncthreads();
    }

    // Epilogue: per-row gather + relu + W2 dot, reduce over n
    int r = lane >> 2, q = (lane & 3) * 2;
    float b2v = __ldg(b2);
#pragma unroll
    for (int mf = 0; mf < 2; ++mf) {
#pragma unroll
        for (int hf = 0; hf < 2; ++hf) {
            int row = wm + mf * 16 + hf * 8 + r;
            int s = sidx[row], t = tidx[row], b = bidx[row];
            const float* As = g_AB + (size_t)s * 256;
            const float* Bsg = g_AB + (size_t)t * 256 + 128;
            const float* Ps = g_P + b * 128;
            float partial = 0.f;
#pragma unroll
            for (int nf = 0; nf < 8; ++nf) {
                int n = wn + nf * 8 + q;
                float2 a2 = *(const float2*)(As + n);
                float2 bb = *(const float2*)(Bsg + n);
                float2 p2 = *(const float2*)(Ps + n);
                float c0 = c[mf][nf][hf * 2 + 0];
                float c1 = c[mf][nf][hf * 2 + 1];
                partial += fmaxf(c0 + a2.x + bb.x + p2.x + b1s[n], 0.f) * W2s[n]
                         + fmaxf(c1 + a2.y + bb.y + p2.y + b1s[n + 1], 0.f) * W2s[n + 1];
            }
            partial += __shfl_xor_sync(0xffffffffu, partial, 1);
            partial += __shfl_xor_sync(0xffffffffu, partial, 2);
            if ((lane & 3) == 0) atomicAdd(&outs[row], partial);
        }
    }
    __syncthreads();
    if (tid < 128) {
        int e = e0 + tid;
        if (e < E) out[e] = outs[tid] + b2v;
    }
}

// ---------------------------------------------------------------------------
extern "C" void kernel_launch(void* const* d_in, const int* in_sizes, int n_in,
                              void* d_out, int out_size) {
    const float* h     = (const float*)d_in[0];
    const int*   ei    = (const int*)d_in[1];     // int32 (JAX x64 disabled)
    const float* ea    = (const float*)d_in[2];
    const int*   batch = (const int*)d_in[3];     // int32
    const float* W1    = (const float*)d_in[4];
    const float* b1    = (const float*)d_in[5];
    const float* W2    = (const float*)d_in[6];
    const float* b2    = (const float*)d_in[7];
    float* out = (float*)d_out;

    int N = in_sizes[0] / ND;
    int E = in_sizes[2] / ED;

    prep_kernel<<<(256 * 256 + 255) / 256, 256>>>(W1);
    offsets_kernel<<<(NUM_GRAPHS + 256) / 256, 256>>>(batch, N);
    pool_kernel<<<NUM_GRAPHS, 128>>>(h, W1);

    float* AB = nullptr; cudaGetSymbolAddress((void**)&AB, g_AB);

    dim3 ngrid((N + 127) / 128, 2);
    node_gemm_fp16<<<ngrid, 256>>>(h, AB, N);

    int eblk = (E + 127) / 128;
    edge_gemm_fused<<<eblk, 256>>>(ea, ei, batch, b1, W2, b2, out, E);
}

// round 16
// speedup vs baseline: 3.0520x; 1.0766x over previous
#include <cuda_runtime.h>
#include <cuda_fp16.h>

#define NUM_GRAPHS 2048
#define ND 256
#define ED 128
#define HD 128
#define MAXN 100000

// Scratch (device globals: allocation-free per harness rules)
__device__ __align__(16) int   g_offsets[NUM_GRAPHS + 1];
__device__ __align__(16) float g_P[NUM_GRAPHS * HD];          // pooled @ W1d [2048,128]
__device__ __align__(16) __half g_ABh[(size_t)MAXN * 256];    // [A'=h@W1a+P+b1 | h@W1b] fp16
__device__ __align__(16) __half g_Bn[256 * 256];              // [W1a|W1b] fp16, k-major
__device__ __align__(16) __half g_Be[128 * 128];              // W1c fp16, k-major

// ---------------------------------------------------------------------------
// mma/ldmatrix helpers
// ---------------------------------------------------------------------------
__device__ __forceinline__ unsigned smem_u32(const void* p) {
    return (unsigned)__cvta_generic_to_shared(p);
}
__device__ __forceinline__ void ldsm4(unsigned addr, unsigned& r0, unsigned& r1,
                                      unsigned& r2, unsigned& r3) {
    asm volatile("ldmatrix.sync.aligned.m8n8.x4.shared.b16 {%0,%1,%2,%3}, [%4];"
                 : "=r"(r0), "=r"(r1), "=r"(r2), "=r"(r3) : "r"(addr));
}
__device__ __forceinline__ void ldsm4t(unsigned addr, unsigned& r0, unsigned& r1,
                                       unsigned& r2, unsigned& r3) {
    asm volatile("ldmatrix.sync.aligned.m8n8.x4.trans.shared.b16 {%0,%1,%2,%3}, [%4];"
                 : "=r"(r0), "=r"(r1), "=r"(r2), "=r"(r3) : "r"(addr));
}
__device__ __forceinline__ void mma16816(float* c, const unsigned* a, const unsigned* b) {
    asm volatile("mma.sync.aligned.m16n8k16.row.col.f32.f16.f16.f32 "
                 "{%0,%1,%2,%3}, {%4,%5,%6,%7}, {%8,%9}, {%0,%1,%2,%3};"
                 : "+f"(c[0]), "+f"(c[1]), "+f"(c[2]), "+f"(c[3])
                 : "r"(a[0]), "r"(a[1]), "r"(a[2]), "r"(a[3]), "r"(b[0]), "r"(b[1]));
}
// fp16 hi/lo split of two fp32 values -> packed half2 regs
__device__ __forceinline__ void split2h(float x0, float x1, unsigned& hi, unsigned& lo) {
    __half h0 = __float2half_rn(x0), h1 = __float2half_rn(x1);
    __half l0 = __float2half_rn(x0 - __half2float(h0));
    __half l1 = __float2half_rn(x1 - __half2float(h1));
    __half2 H = __halves2half2(h0, h1), L = __halves2half2(l0, l1);
    hi = *(unsigned*)&H;
    lo = *(unsigned*)&L;
}

// ---------------------------------------------------------------------------
// Kernel 0: weights -> fp16, k-major
// ---------------------------------------------------------------------------
__global__ void prep_kernel(const float* __restrict__ W1) {
    int idx = blockIdx.x * blockDim.x + threadIdx.x;
    if (idx < 256 * 256) {
        int k = idx >> 8, n = idx & 255;
        float w = (n < 128) ? W1[(size_t)k * 128 + n]
                            : W1[(size_t)(256 + k) * 128 + (n - 128)];
        g_Bn[idx] = __float2half_rn(w);
    }
    if (idx < 128 * 128) {
        int k = idx >> 7, n = idx & 127;
        g_Be[idx] = __float2half_rn(W1[(size_t)(512 + k) * 128 + n]);
    }
}

// ---------------------------------------------------------------------------
// Kernel 1: graph start offsets via binary search (batch is sorted int32)
// ---------------------------------------------------------------------------
__global__ void offsets_kernel(const int* __restrict__ batch, int N) {
    int g = blockIdx.x * blockDim.x + threadIdx.x;
    if (g > NUM_GRAPHS) return;
    int lo = 0, hi = N;
    while (lo < hi) {
        int mid = (lo + hi) >> 1;
        if (batch[mid] < g) lo = mid + 1; else hi = mid;
    }
    g_offsets[g] = lo;
}

// ---------------------------------------------------------------------------
// Kernel 2: per-graph mean pooling + P = pooled @ W1d (W1 rows 640..895)
// ---------------------------------------------------------------------------
__global__ void pool_kernel(const float* __restrict__ h, const float* __restrict__ W1) {
    __shared__ float pool_s[ND];
    int g = blockIdx.x;
    int tid = threadIdx.x;
    int o0 = g_offsets[g], o1 = g_offsets[g + 1];
    float s0 = 0.f, s1 = 0.f;
    int r = o0;
    for (; r + 1 < o1; r += 2) {
        const float* row0 = h + (size_t)r * ND;
        const float* row1 = row0 + ND;
        s0 += row0[tid] + row1[tid];
        s1 += row0[tid + 128] + row1[tid + 128];
    }
    if (r < o1) {
        const float* row = h + (size_t)r * ND;
        s0 += row[tid];
        s1 += row[tid + 128];
    }
    int cnt = o1 - o0;
    float inv = 1.f / (float)(cnt > 1 ? cnt : 1);
    pool_s[tid]       = s0 * inv;
    pool_s[tid + 128] = s1 * inv;
    __syncthreads();
    float acc = 0.f;
    const float* Wg = W1 + (size_t)640 * HD;
#pragma unroll 8
    for (int k = 0; k < ND; ++k) acc += pool_s[k] * Wg[k * HD + tid];
    g_P[g * HD + tid] = acc;
}

// ---------------------------------------------------------------------------
// Kernel 3: node GEMM, fp16 2-term split (A=hi+lo, B=fp16).
// block tile 128m x 128n (grid.y selects half), 256 thr = 8 warps (4m x 2n).
// Epilogue: half 0 adds P[batch[m]] + b1, both halves store fp16 into g_ABh.
// ---------------------------------------------------------------------------
__global__ __launch_bounds__(256, 2) void node_gemm_fp16(const float* __restrict__ h,
                                                         const int* __restrict__ batch,
                                                         const float* __restrict__ b1,
                                                         int M) {
    __shared__ __half Ahi[2][128 * 24], Alo[2][128 * 24];
    __shared__ __half Bs[2][16 * 136];

    int tid = threadIdx.x;
    int wid = tid >> 5, lane = tid & 31;
    int wm = (wid & 3) * 32, wn = (wid >> 2) * 64;
    int m0 = blockIdx.x * 128;
    int nb = blockIdx.y * 128;
    const __half* Bg = g_Bn + nb;

    float c[2][8][4];
#pragma unroll
    for (int mf = 0; mf < 2; ++mf)
#pragma unroll
        for (int nf = 0; nf < 8; ++nf)
#pragma unroll
            for (int q = 0; q < 4; ++q) c[mf][nf][q] = 0.f;

    int l15 = lane & 15, l16 = lane >> 4;
    unsigned aOff = ((wm + l15) * 24 + l16 * 8) * 2;
    unsigned bOff = (l15 * 136 + wn + l16 * 8) * 2;

    int am = tid >> 1, half = tid & 1;         // A loader: 8 floats
    int br = tid >> 4, bc = (tid & 15) * 8;    // B loader: 8 fp16

    const float* Aptr = h + (size_t)(m0 + am) * 256 + half * 8;
    bool aValid = (m0 + am) < M;

    float4 v0 = make_float4(0.f, 0.f, 0.f, 0.f), v1 = v0;
    if (aValid) { v0 = *(const float4*)(Aptr); v1 = *(const float4*)(Aptr + 4); }
    uint4 bv = *(const uint4*)&Bg[(size_t)br * 256 + bc];
    {
        unsigned h01, l01, h23, l23, h45, l45, h67, l67;
        split2h(v0.x, v0.y, h01, l01); split2h(v0.z, v0.w, h23, l23);
        split2h(v1.x, v1.y, h45, l45); split2h(v1.z, v1.w, h67, l67);
        *(uint4*)&Ahi[0][am * 24 + half * 8] = make_uint4(h01, h23, h45, h67);
        *(uint4*)&Alo[0][am * 24 + half * 8] = make_uint4(l01, l23, l45, l67);
        *(uint4*)&Bs[0][br * 136 + bc] = bv;
    }
    __syncthreads();

    for (int kt = 0; kt < 16; ++kt) {
        int buf = kt & 1;
        if (kt + 1 < 16) {
            if (aValid) {
                const float* src = Aptr + (kt + 1) * 16;
                v0 = *(const float4*)(src);
                v1 = *(const float4*)(src + 4);
            }
            bv = *(const uint4*)&Bg[(size_t)((kt + 1) * 16 + br) * 256 + bc];
        }

        unsigned ah[2][4], al[2][4];
        unsigned aBase = smem_u32(Ahi[buf]), aBaseL = smem_u32(Alo[buf]);
        ldsm4(aBase + aOff,            ah[0][0], ah[0][1], ah[0][2], ah[0][3]);
        ldsm4(aBase + aOff + 16 * 48,  ah[1][0], ah[1][1], ah[1][2], ah[1][3]);
        ldsm4(aBaseL + aOff,           al[0][0], al[0][1], al[0][2], al[0][3]);
        ldsm4(aBaseL + aOff + 16 * 48, al[1][0], al[1][1], al[1][2], al[1][3]);
        unsigned bBase = smem_u32(Bs[buf]) + bOff;
#pragma unroll
        for (int nf2 = 0; nf2 < 4; ++nf2) {
            unsigned b4[4];
            ldsm4t(bBase + nf2 * 32, b4[0], b4[1], b4[2], b4[3]);
#pragma unroll
            for (int mf = 0; mf < 2; ++mf) {
                mma16816(c[mf][2 * nf2],     ah[mf], b4);
                mma16816(c[mf][2 * nf2],     al[mf], b4);
                mma16816(c[mf][2 * nf2 + 1], ah[mf], b4 + 2);
                mma16816(c[mf][2 * nf2 + 1], al[mf], b4 + 2);
            }
        }

        if (kt + 1 < 16) {
            unsigned h01, l01, h23, l23, h45, l45, h67, l67;
            split2h(v0.x, v0.y, h01, l01); split2h(v0.z, v0.w, h23, l23);
            split2h(v1.x, v1.y, h45, l45); split2h(v1.z, v1.w, h67, l67);
            *(uint4*)&Ahi[buf ^ 1][am * 24 + half * 8] = make_uint4(h01, h23, h45, h67);
            *(uint4*)&Alo[buf ^ 1][am * 24 + half * 8] = make_uint4(l01, l23, l45, l67);
            *(uint4*)&Bs[buf ^ 1][br * 136 + bc] = bv;
        }
        __syncthreads();
    }

    int r = lane >> 2, q = (lane & 3) * 2;
    if (nb == 0) {
        // A' half: add P[batch[m]] + b1, quantize, store
#pragma unroll
        for (int mf = 0; mf < 2; ++mf) {
            int m1 = m0 + wm + mf * 16 + r;
            int m2 = m1 + 8;
            int bg1 = (m1 < M) ? __ldg(&batch[m1]) : 0;
            int bg2 = (m2 < M) ? __ldg(&batch[m2]) : 0;
            const float* P1 = g_P + bg1 * 128;
            const float* P2 = g_P + bg2 * 128;
#pragma unroll
            for (int nf = 0; nf < 8; ++nf) {
                int n = wn + nf * 8 + q;
                float2 bi = *(const float2*)(b1 + n);
                if (m1 < M) {
                    float2 p = *(const float2*)(P1 + n);
                    __half2 hv = __floats2half2_rn(c[mf][nf][0] + p.x + bi.x,
                                                   c[mf][nf][1] + p.y + bi.y);
                    *(__half2*)&g_ABh[(size_t)m1 * 256 + n] = hv;
                }
                if (m2 < M) {
                    float2 p = *(const float2*)(P2 + n);
                    __half2 hv = __floats2half2_rn(c[mf][nf][2] + p.x + bi.x,
                                                   c[mf][nf][3] + p.y + bi.y);
                    *(__half2*)&g_ABh[(size_t)m2 * 256 + n] = hv;
                }
            }
        }
    } else {
        // B half: plain quantize + store at cols 128..255
#pragma unroll
        for (int mf = 0; mf < 2; ++mf) {
            int m1 = m0 + wm + mf * 16 + r;
            int m2 = m1 + 8;
#pragma unroll
            for (int nf = 0; nf < 8; ++nf) {
                int n = wn + nf * 8 + q;
                if (m1 < M)
                    *(__half2*)&g_ABh[(size_t)m1 * 256 + 128 + n] =
                        __floats2half2_rn(c[mf][nf][0], c[mf][nf][1]);
                if (m2 < M)
                    *(__half2*)&g_ABh[(size_t)m2 * 256 + 128 + n] =
                        __floats2half2_rn(c[mf][nf][2], c[mf][nf][3]);
            }
        }
    }
}

// ---------------------------------------------------------------------------
// Kernel 4: fused edge GEMM (fp16 2-term) + epilogue.
//   hid = relu(EC + A'[s] + B[t]);  out[e] = hid . W2 + b2
// ---------------------------------------------------------------------------
__global__ __launch_bounds__(256, 2) void edge_gemm_fused(const float* __restrict__ ea,
                                                          const int* __restrict__ ei,
                                                          const float* __restrict__ W2,
                                                          const float* __restrict__ b2,
                                                          float* __restrict__ out, int E) {
    __shared__ __half Ahi[2][128 * 24], Alo[2][128 * 24];
    __shared__ __half Bs[2][16 * 136];
    __shared__ int sidx[128], tidx[128];
    __shared__ float outs[128], W2s[128];

    int tid = threadIdx.x;
    int wid = tid >> 5, lane = tid & 31;
    int wm = (wid & 3) * 32, wn = (wid >> 2) * 64;
    int e0 = blockIdx.x * 128;

    if (tid < 128) {
        W2s[tid] = W2[tid];
        outs[tid] = 0.f;
        int e = e0 + tid;
        int s = 0, t = 0;
        if (e < E) {
            s = __ldg(&ei[e]);
            t = __ldg(&ei[E + e]);
        }
        sidx[tid] = s; tidx[tid] = t;
    }

    float c[2][8][4];
#pragma unroll
    for (int mf = 0; mf < 2; ++mf)
#pragma unroll
        for (int nf = 0; nf < 8; ++nf)
#pragma unroll
            for (int q = 0; q < 4; ++q) c[mf][nf][q] = 0.f;

    int l15 = lane & 15, l16 = lane >> 4;
    unsigned aOff = ((wm + l15) * 24 + l16 * 8) * 2;
    unsigned bOff = (l15 * 136 + wn + l16 * 8) * 2;

    int am = tid >> 1, half = tid & 1;
    int br = tid >> 4, bc = (tid & 15) * 8;

    const float* Aptr = ea + (size_t)(e0 + am) * 128 + half * 8;
    bool aValid = (e0 + am) < E;

    float4 v0 = make_float4(0.f, 0.f, 0.f, 0.f), v1 = v0;
    if (aValid) { v0 = *(const float4*)(Aptr); v1 = *(const float4*)(Aptr + 4); }
    uint4 bv = *(const uint4*)&g_Be[(size_t)br * 128 + bc];
    {
        unsigned h01, l01, h23, l23, h45, l45, h67, l67;
        split2h(v0.x, v0.y, h01, l01); split2h(v0.z, v0.w, h23, l23);
        split2h(v1.x, v1.y, h45, l45); split2h(v1.z, v1.w, h67, l67);
        *(uint4*)&Ahi[0][am * 24 + half * 8] = make_uint4(h01, h23, h45, h67);
        *(uint4*)&Alo[0][am * 24 + half * 8] = make_uint4(l01, l23, l45, l67);
        *(uint4*)&Bs[0][br * 136 + bc] = bv;
    }
    __syncthreads();

    for (int kt = 0; kt < 8; ++kt) {
        int buf = kt & 1;
        if (kt + 1 < 8) {
            if (aValid) {
                const float* src = Aptr + (kt + 1) * 16;
                v0 = *(const float4*)(src);
                v1 = *(const float4*)(src + 4);
            }
            bv = *(const uint4*)&g_Be[(size_t)((kt + 1) * 16 + br) * 128 + bc];
        }

        unsigned ah[2][4], al[2][4];
        unsigned aBase = smem_u32(Ahi[buf]), aBaseL = smem_u32(Alo[buf]);
        ldsm4(aBase + aOff,            ah[0][0], ah[0][1], ah[0][2], ah[0][3]);
        ldsm4(aBase + aOff + 16 * 48,  ah[1][0], ah[1][1], ah[1][2], ah[1][3]);
        ldsm4(aBaseL + aOff,           al[0][0], al[0][1], al[0][2], al[0][3]);
        ldsm4(aBaseL + aOff + 16 * 48, al[1][0], al[1][1], al[1][2], al[1][3]);
        unsigned bBase = smem_u32(Bs[buf]) + bOff;
#pragma unroll
        for (int nf2 = 0; nf2 < 4; ++nf2) {
            unsigned b4[4];
            ldsm4t(bBase + nf2 * 32, b4[0], b4[1], b4[2], b4[3]);
#pragma unroll
            for (int mf = 0; mf < 2; ++mf) {
                mma16816(c[mf][2 * nf2],     ah[mf], b4);
                mma16816(c[mf][2 * nf2],     al[mf], b4);
                mma16816(c[mf][2 * nf2 + 1], ah[mf], b4 + 2);
                mma16816(c[mf][2 * nf2 + 1], al[mf], b4 + 2);
            }
        }

        if (kt + 1 < 8) {
            unsigned h01, l01, h23, l23, h45, l45, h67, l67;
            split2h(v0.x, v0.y, h01, l01); split2h(v0.z, v0.w, h23, l23);
            split2h(v1.x, v1.y, h45, l45); split2h(v1.z, v1.w, h67, l67);
            *(uint4*)&Ahi[buf ^ 1][am * 24 + half * 8] = make_uint4(h01, h23, h45, h67);
            *(uint4*)&Alo[buf ^ 1][am * 24 + half * 8] = make_uint4(l01, l23, l45, l67);
            *(uint4*)&Bs[buf ^ 1][br * 136 + bc] = bv;
        }
        __syncthreads();
    }

    // Epilogue: per-row fp16 gathers + relu + W2 dot, reduce over n
    int r = lane >> 2, q = (lane & 3) * 2;
    float b2v = __ldg(b2);
#pragma unroll
    for (int mf = 0; mf < 2; ++mf) {
#pragma unroll
        for (int hf = 0; hf < 2; ++hf) {
            int row = wm + mf * 16 + hf * 8 + r;
            int s = sidx[row], t = tidx[row];
            const __half* As = g_ABh + (size_t)s * 256;
            const __half* Bg = g_ABh + (size_t)t * 256 + 128;
            float partial = 0.f;
#pragma unroll
            for (int nf = 0; nf < 8; ++nf) {
                int n = wn + nf * 8 + q;
                float2 a2 = __half22float2(*(const __half2*)(As + n));
                float2 bb = __half22float2(*(const __half2*)(Bg + n));
                float c0 = c[mf][nf][hf * 2 + 0];
                float c1 = c[mf][nf][hf * 2 + 1];
                partial += fmaxf(c0 + a2.x + bb.x, 0.f) * W2s[n]
                         + fmaxf(c1 + a2.y + bb.y, 0.f) * W2s[n + 1];
            }
            partial += __shfl_xor_sync(0xffffffffu, partial, 1);
            partial += __shfl_xor_sync(0xffffffffu, partial, 2);
            if ((lane & 3) == 0) atomicAdd(&outs[row], partial);
        }
    }
    __syncthreads();
    if (tid < 128) {
        int e = e0 + tid;
        if (e < E) out[e] = outs[tid] + b2v;
    }
}

// ---------------------------------------------------------------------------
extern "C" void kernel_launch(void* const* d_in, const int* in_sizes, int n_in,
                              void* d_out, int out_size) {
    const float* h     = (const float*)d_in[0];
    const int*   ei    = (const int*)d_in[1];     // int32 (JAX x64 disabled)
    const float* ea    = (const float*)d_in[2];
    const int*   batch = (const int*)d_in[3];     // int32
    const float* W1    = (const float*)d_in[4];
    const float* b1    = (const float*)d_in[5];
    const float* W2    = (const float*)d_in[6];
    const float* b2    = (const float*)d_in[7];
    float* out = (float*)d_out;

    int N = in_sizes[0] / ND;
    int E = in_sizes[2] / ED;

    prep_kernel<<<(256 * 256 + 255) / 256, 256>>>(W1);
    offsets_kernel<<<(NUM_GRAPHS + 256) / 256, 256>>>(batch, N);
    pool_kernel<<<NUM_GRAPHS, 128>>>(h, W1);

    dim3 ngrid((N + 127) / 128, 2);
    node_gemm_fp16<<<ngrid, 256>>>(h, batch, b1, N);

    int eblk = (E + 127) / 128;
    edge_gemm_fused<<<eblk, 256>>>(ea, ei, W2, b2, out, E);
}

// round 17
// speedup vs baseline: 3.3796x; 1.1073x over previous
#include <cuda_runtime.h>
#include <cuda_fp16.h>

#define NUM_GRAPHS 2048
#define ND 256
#define ED 128
#define HD 128
#define MAXN 100000

// Scratch (device globals: allocation-free per harness rules)
__device__ __align__(16) int   g_offsets[NUM_GRAPHS + 1];
__device__ __align__(16) float g_P[NUM_GRAPHS * HD];          // pooled @ W1d [2048,128]
__device__ __align__(16) __half g_ABh[(size_t)MAXN * 256];    // [A'=h@W1a+P+b1 | h@W1b] fp16
__device__ __align__(16) __half g_Bn[256 * 256];              // [W1a|W1b] fp16, k-major
__device__ __align__(16) __half g_Be[128 * 128];              // W1c fp16, k-major

// ---------------------------------------------------------------------------
// mma/ldmatrix helpers
// ---------------------------------------------------------------------------
__device__ __forceinline__ unsigned smem_u32(const void* p) {
    return (unsigned)__cvta_generic_to_shared(p);
}
__device__ __forceinline__ void ldsm4(unsigned addr, unsigned& r0, unsigned& r1,
                                      unsigned& r2, unsigned& r3) {
    asm volatile("ldmatrix.sync.aligned.m8n8.x4.shared.b16 {%0,%1,%2,%3}, [%4];"
                 : "=r"(r0), "=r"(r1), "=r"(r2), "=r"(r3) : "r"(addr));
}
__device__ __forceinline__ void ldsm4t(unsigned addr, unsigned& r0, unsigned& r1,
                                       unsigned& r2, unsigned& r3) {
    asm volatile("ldmatrix.sync.aligned.m8n8.x4.trans.shared.b16 {%0,%1,%2,%3}, [%4];"
                 : "=r"(r0), "=r"(r1), "=r"(r2), "=r"(r3) : "r"(addr));
}
__device__ __forceinline__ void mma16816(float* c, const unsigned* a, const unsigned* b) {
    asm volatile("mma.sync.aligned.m16n8k16.row.col.f32.f16.f16.f32 "
                 "{%0,%1,%2,%3}, {%4,%5,%6,%7}, {%8,%9}, {%0,%1,%2,%3};"
                 : "+f"(c[0]), "+f"(c[1]), "+f"(c[2]), "+f"(c[3])
                 : "r"(a[0]), "r"(a[1]), "r"(a[2]), "r"(a[3]), "r"(b[0]), "r"(b[1]));
}
// pack two fp32 -> half2 reg
__device__ __forceinline__ unsigned cvt2h(float x0, float x1) {
    __half2 H = __floats2half2_rn(x0, x1);
    return *(unsigned*)&H;
}

// ---------------------------------------------------------------------------
// Kernel 0: weights -> fp16, k-major
// ---------------------------------------------------------------------------
__global__ void prep_kernel(const float* __restrict__ W1) {
    int idx = blockIdx.x * blockDim.x + threadIdx.x;
    if (idx < 256 * 256) {
        int k = idx >> 8, n = idx & 255;
        float w = (n < 128) ? W1[(size_t)k * 128 + n]
                            : W1[(size_t)(256 + k) * 128 + (n - 128)];
        g_Bn[idx] = __float2half_rn(w);
    }
    if (idx < 128 * 128) {
        int k = idx >> 7, n = idx & 127;
        g_Be[idx] = __float2half_rn(W1[(size_t)(512 + k) * 128 + n]);
    }
}

// ---------------------------------------------------------------------------
// Kernel 1: graph start offsets via binary search (batch is sorted int32)
// ---------------------------------------------------------------------------
__global__ void offsets_kernel(const int* __restrict__ batch, int N) {
    int g = blockIdx.x * blockDim.x + threadIdx.x;
    if (g > NUM_GRAPHS) return;
    int lo = 0, hi = N;
    while (lo < hi) {
        int mid = (lo + hi) >> 1;
        if (batch[mid] < g) lo = mid + 1; else hi = mid;
    }
    g_offsets[g] = lo;
}

// ---------------------------------------------------------------------------
// Kernel 2: per-graph mean pooling + P = pooled @ W1d (W1 rows 640..895)
// ---------------------------------------------------------------------------
__global__ void pool_kernel(const float* __restrict__ h, const float* __restrict__ W1) {
    __shared__ float pool_s[ND];
    int g = blockIdx.x;
    int tid = threadIdx.x;
    int o0 = g_offsets[g], o1 = g_offsets[g + 1];
    float s0 = 0.f, s1 = 0.f;
    int r = o0;
    for (; r + 1 < o1; r += 2) {
        const float* row0 = h + (size_t)r * ND;
        const float* row1 = row0 + ND;
        s0 += row0[tid] + row1[tid];
        s1 += row0[tid + 128] + row1[tid + 128];
    }
    if (r < o1) {
        const float* row = h + (size_t)r * ND;
        s0 += row[tid];
        s1 += row[tid + 128];
    }
    int cnt = o1 - o0;
    float inv = 1.f / (float)(cnt > 1 ? cnt : 1);
    pool_s[tid]       = s0 * inv;
    pool_s[tid + 128] = s1 * inv;
    __syncthreads();
    float acc = 0.f;
    const float* Wg = W1 + (size_t)640 * HD;
#pragma unroll 8
    for (int k = 0; k < ND; ++k) acc += pool_s[k] * Wg[k * HD + tid];
    g_P[g * HD + tid] = acc;
}

// ---------------------------------------------------------------------------
// Kernel 3: node GEMM, single-fp16 A x fp16 B.
// block tile 128m x 128n (grid.y selects half), 256 thr = 8 warps (4m x 2n).
// Epilogue: half 0 adds P[batch[m]] + b1, both halves store fp16 into g_ABh.
// ---------------------------------------------------------------------------
__global__ __launch_bounds__(256, 2) void node_gemm_fp16(const float* __restrict__ h,
                                                         const int* __restrict__ batch,
                                                         const float* __restrict__ b1,
                                                         int M) {
    __shared__ __half As[2][128 * 24];
    __shared__ __half Bs[2][16 * 136];

    int tid = threadIdx.x;
    int wid = tid >> 5, lane = tid & 31;
    int wm = (wid & 3) * 32, wn = (wid >> 2) * 64;
    int m0 = blockIdx.x * 128;
    int nb = blockIdx.y * 128;
    const __half* Bg = g_Bn + nb;

    float c[2][8][4];
#pragma unroll
    for (int mf = 0; mf < 2; ++mf)
#pragma unroll
        for (int nf = 0; nf < 8; ++nf)
#pragma unroll
            for (int q = 0; q < 4; ++q) c[mf][nf][q] = 0.f;

    int l15 = lane & 15, l16 = lane >> 4;
    unsigned aOff = ((wm + l15) * 24 + l16 * 8) * 2;
    unsigned bOff = (l15 * 136 + wn + l16 * 8) * 2;

    int am = tid >> 1, half = tid & 1;         // A loader: 8 floats
    int br = tid >> 4, bc = (tid & 15) * 8;    // B loader: 8 fp16

    const float* Aptr = h + (size_t)(m0 + am) * 256 + half * 8;
    bool aValid = (m0 + am) < M;

    float4 v0 = make_float4(0.f, 0.f, 0.f, 0.f), v1 = v0;
    if (aValid) { v0 = *(const float4*)(Aptr); v1 = *(const float4*)(Aptr + 4); }
    uint4 bv = *(const uint4*)&Bg[(size_t)br * 256 + bc];
    *(uint4*)&As[0][am * 24 + half * 8] =
        make_uint4(cvt2h(v0.x, v0.y), cvt2h(v0.z, v0.w),
                   cvt2h(v1.x, v1.y), cvt2h(v1.z, v1.w));
    *(uint4*)&Bs[0][br * 136 + bc] = bv;
    __syncthreads();

    for (int kt = 0; kt < 16; ++kt) {
        int buf = kt & 1;
        if (kt + 1 < 16) {
            if (aValid) {
                const float* src = Aptr + (kt + 1) * 16;
                v0 = *(const float4*)(src);
                v1 = *(const float4*)(src + 4);
            }
            bv = *(const uint4*)&Bg[(size_t)((kt + 1) * 16 + br) * 256 + bc];
        }

        unsigned ah[2][4];
        unsigned aBase = smem_u32(As[buf]);
        ldsm4(aBase + aOff,           ah[0][0], ah[0][1], ah[0][2], ah[0][3]);
        ldsm4(aBase + aOff + 16 * 48, ah[1][0], ah[1][1], ah[1][2], ah[1][3]);
        unsigned bBase = smem_u32(Bs[buf]) + bOff;
#pragma unroll
        for (int nf2 = 0; nf2 < 4; ++nf2) {
            unsigned b4[4];
            ldsm4t(bBase + nf2 * 32, b4[0], b4[1], b4[2], b4[3]);
#pragma unroll
            for (int mf = 0; mf < 2; ++mf) {
                mma16816(c[mf][2 * nf2],     ah[mf], b4);
                mma16816(c[mf][2 * nf2 + 1], ah[mf], b4 + 2);
            }
        }

        if (kt + 1 < 16) {
            *(uint4*)&As[buf ^ 1][am * 24 + half * 8] =
                make_uint4(cvt2h(v0.x, v0.y), cvt2h(v0.z, v0.w),
                           cvt2h(v1.x, v1.y), cvt2h(v1.z, v1.w));
            *(uint4*)&Bs[buf ^ 1][br * 136 + bc] = bv;
        }
        __syncthreads();
    }

    int r = lane >> 2, q = (lane & 3) * 2;
    if (nb == 0) {
        // A' half: add P[batch[m]] + b1, quantize, store
#pragma unroll
        for (int mf = 0; mf < 2; ++mf) {
            int m1 = m0 + wm + mf * 16 + r;
            int m2 = m1 + 8;
            int bg1 = (m1 < M) ? __ldg(&batch[m1]) : 0;
            int bg2 = (m2 < M) ? __ldg(&batch[m2]) : 0;
            const float* P1 = g_P + bg1 * 128;
            const float* P2 = g_P + bg2 * 128;
#pragma unroll
            for (int nf = 0; nf < 8; ++nf) {
                int n = wn + nf * 8 + q;
                float2 bi = *(const float2*)(b1 + n);
                if (m1 < M) {
                    float2 p = *(const float2*)(P1 + n);
                    *(__half2*)&g_ABh[(size_t)m1 * 256 + n] =
                        __floats2half2_rn(c[mf][nf][0] + p.x + bi.x,
                                          c[mf][nf][1] + p.y + bi.y);
                }
                if (m2 < M) {
                    float2 p = *(const float2*)(P2 + n);
                    *(__half2*)&g_ABh[(size_t)m2 * 256 + n] =
                        __floats2half2_rn(c[mf][nf][2] + p.x + bi.x,
                                          c[mf][nf][3] + p.y + bi.y);
                }
            }
        }
    } else {
        // B half: plain quantize + store at cols 128..255
#pragma unroll
        for (int mf = 0; mf < 2; ++mf) {
            int m1 = m0 + wm + mf * 16 + r;
            int m2 = m1 + 8;
#pragma unroll
            for (int nf = 0; nf < 8; ++nf) {
                int n = wn + nf * 8 + q;
                if (m1 < M)
                    *(__half2*)&g_ABh[(size_t)m1 * 256 + 128 + n] =
                        __floats2half2_rn(c[mf][nf][0], c[mf][nf][1]);
                if (m2 < M)
                    *(__half2*)&g_ABh[(size_t)m2 * 256 + 128 + n] =
                        __floats2half2_rn(c[mf][nf][2], c[mf][nf][3]);
            }
        }
    }
}

// ---------------------------------------------------------------------------
// Kernel 4: fused edge GEMM (single-fp16 A) + epilogue.
//   hid = relu(EC + A'[s] + B[t]);  out[e] = hid . W2 + b2
// ---------------------------------------------------------------------------
__global__ __launch_bounds__(256, 2) void edge_gemm_fused(const float* __restrict__ ea,
                                                          const int* __restrict__ ei,
                                                          const float* __restrict__ W2,
                                                          const float* __restrict__ b2,
                                                          float* __restrict__ out, int E) {
    __shared__ __half As[2][128 * 24];
    __shared__ __half Bs[2][16 * 136];
    __shared__ int sidx[128], tidx[128];
    __shared__ float outs[128], W2s[128];

    int tid = threadIdx.x;
    int wid = tid >> 5, lane = tid & 31;
    int wm = (wid & 3) * 32, wn = (wid >> 2) * 64;
    int e0 = blockIdx.x * 128;

    if (tid < 128) {
        W2s[tid] = W2[tid];
        outs[tid] = 0.f;
        int e = e0 + tid;
        int s = 0, t = 0;
        if (e < E) {
            s = __ldg(&ei[e]);
            t = __ldg(&ei[E + e]);
        }
        sidx[tid] = s; tidx[tid] = t;
    }

    float c[2][8][4];
#pragma unroll
    for (int mf = 0; mf < 2; ++mf)
#pragma unroll
        for (int nf = 0; nf < 8; ++nf)
#pragma unroll
            for (int q = 0; q < 4; ++q) c[mf][nf][q] = 0.f;

    int l15 = lane & 15, l16 = lane >> 4;
    unsigned aOff = ((wm + l15) * 24 + l16 * 8) * 2;
    unsigned bOff = (l15 * 136 + wn + l16 * 8) * 2;

    int am = tid >> 1, half = tid & 1;
    int br = tid >> 4, bc = (tid & 15) * 8;

    const float* Aptr = ea + (size_t)(e0 + am) * 128 + half * 8;
    bool aValid = (e0 + am) < E;

    float4 v0 = make_float4(0.f, 0.f, 0.f, 0.f), v1 = v0;
    if (aValid) { v0 = *(const float4*)(Aptr); v1 = *(const float4*)(Aptr + 4); }
    uint4 bv = *(const uint4*)&g_Be[(size_t)br * 128 + bc];
    *(uint4*)&As[0][am * 24 + half * 8] =
        make_uint4(cvt2h(v0.x, v0.y), cvt2h(v0.z, v0.w),
                   cvt2h(v1.x, v1.y), cvt2h(v1.z, v1.w));
    *(uint4*)&Bs[0][br * 136 + bc] = bv;
    __syncthreads();

    for (int kt = 0; kt < 8; ++kt) {
        int buf = kt & 1;
        if (kt + 1 < 8) {
            if (aValid) {
                const float* src = Aptr + (kt + 1) * 16;
                v0 = *(const float4*)(src);
                v1 = *(const float4*)(src + 4);
            }
            bv = *(const uint4*)&g_Be[(size_t)((kt + 1) * 16 + br) * 128 + bc];
        }

        unsigned ah[2][4];
        unsigned aBase = smem_u32(As[buf]);
        ldsm4(aBase + aOff,           ah[0][0], ah[0][1], ah[0][2], ah[0][3]);
        ldsm4(aBase + aOff + 16 * 48, ah[1][0], ah[1][1], ah[1][2], ah[1][3]);
        unsigned bBase = smem_u32(Bs[buf]) + bOff;
#pragma unroll
        for (int nf2 = 0; nf2 < 4; ++nf2) {
            unsigned b4[4];
            ldsm4t(bBase + nf2 * 32, b4[0], b4[1], b4[2], b4[3]);
#pragma unroll
            for (int mf = 0; mf < 2; ++mf) {
                mma16816(c[mf][2 * nf2],     ah[mf], b4);
                mma16816(c[mf][2 * nf2 + 1], ah[mf], b4 + 2);
            }
        }

        if (kt + 1 < 8) {
            *(uint4*)&As[buf ^ 1][am * 24 + half * 8] =
                make_uint4(cvt2h(v0.x, v0.y), cvt2h(v0.z, v0.w),
                           cvt2h(v1.x, v1.y), cvt2h(v1.z, v1.w));
            *(uint4*)&Bs[buf ^ 1][br * 136 + bc] = bv;
        }
        __syncthreads();
    }

    // Epilogue: per-row fp16 gathers + relu + W2 dot, reduce over n
    int r = lane >> 2, q = (lane & 3) * 2;
    float b2v = __ldg(b2);
#pragma unroll
    for (int mf = 0; mf < 2; ++mf) {
#pragma unroll
        for (int hf = 0; hf < 2; ++hf) {
            int row = wm + mf * 16 + hf * 8 + r;
            int s = sidx[row], t = tidx[row];
            const __half* Asg = g_ABh + (size_t)s * 256;
            const __half* Bg = g_ABh + (size_t)t * 256 + 128;
            float partial = 0.f;
#pragma unroll
            for (int nf = 0; nf < 8; ++nf) {
                int n = wn + nf * 8 + q;
                float2 a2 = __half22float2(*(const __half2*)(Asg + n));
                float2 bb = __half22float2(*(const __half2*)(Bg + n));
                float c0 = c[mf][nf][hf * 2 + 0];
                float c1 = c[mf][nf][hf * 2 + 1];
                partial += fmaxf(c0 + a2.x + bb.x, 0.f) * W2s[n]
                         + fmaxf(c1 + a2.y + bb.y, 0.f) * W2s[n + 1];
            }
            partial += __shfl_xor_sync(0xffffffffu, partial, 1);
            partial += __shfl_xor_sync(0xffffffffu, partial, 2);
            if ((lane & 3) == 0) atomicAdd(&outs[row], partial);
        }
    }
    __syncthreads();
    if (tid < 128) {
        int e = e0 + tid;
        if (e < E) out[e] = outs[tid] + b2v;
    }
}

// ---------------------------------------------------------------------------
extern "C" void kernel_launch(void* const* d_in, const int* in_sizes, int n_in,
                              void* d_out, int out_size) {
    const float* h     = (const float*)d_in[0];
    const int*   ei    = (const int*)d_in[1];     // int32 (JAX x64 disabled)
    const float* ea    = (const float*)d_in[2];
    const int*   batch = (const int*)d_in[3];     // int32
    const float* W1    = (const float*)d_in[4];
    const float* b1    = (const float*)d_in[5];
    const float* W2    = (const float*)d_in[6];
    const float* b2    = (const float*)d_in[7];
    float* out = (float*)d_out;

    int N = in_sizes[0] / ND;
    int E = in_sizes[2] / ED;

    prep_kernel<<<(256 * 256 + 255) / 256, 256>>>(W1);
    offsets_kernel<<<(NUM_GRAPHS + 256) / 256, 256>>>(batch, N);
    pool_kernel<<<NUM_GRAPHS, 128>>>(h, W1);

    dim3 ngrid((N + 127) / 128, 2);
    node_gemm_fp16<<<ngrid, 256>>>(h, batch, b1, N);

    int eblk = (E + 127) / 128;
    edge_gemm_fused<<<eblk, 256>>>(ea, ei, W2, b2, out, E);
}